// round 1
// baseline (speedup 1.0000x reference)
#include <cuda_runtime.h>

// Problem constants (fixed by the dataset)
#define B_ 4
#define T_ 2048
#define D_ 1024
#define H_ 16
#define S_ 64
#define M_ (B_ * T_)   // 8192 rows

// Scratch (static device allocations are allowed; runtime allocs are not)
__device__ float g_q[(size_t)M_ * D_];     // q = x @ Wq^T, layout (b, t, d)
__device__ float g_attn[(size_t)M_ * D_];  // merged attention output, layout (b, t, d)

// ---------------------------------------------------------------------------
// Tiled fp32 GEMM: C[m][n] = sum_k A[m][k] * W[n][k]  (+ optional bias[n])
// A: M x K row-major, W: N x K row-major (torch Linear weight), K=N=1024.
// Tile 64x64, BK=16, 256 threads, 4x4 per thread.
// ---------------------------------------------------------------------------
__device__ __forceinline__ void gemm64(const float* __restrict__ A,
                                       const float* __restrict__ W,
                                       const float* __restrict__ bias,
                                       float* __restrict__ C)
{
    constexpr int K = 1024, N = 1024;
    __shared__ float As[64][17];
    __shared__ float Ws[64][17];

    const int tid = threadIdx.x;
    const int tx = tid & 15;
    const int ty = tid >> 4;
    const int m0 = blockIdx.y << 6;
    const int n0 = blockIdx.x << 6;

    // loader mapping: 4 threads per row, 4 consecutive floats each (float4)
    const int lr = tid >> 2;
    const int lc = (tid & 3) << 2;
    const float* Ag = A + (size_t)(m0 + lr) * K + lc;
    const float* Wg = W + (size_t)(n0 + lr) * K + lc;

    float acc[4][4] = {};

    for (int k0 = 0; k0 < K; k0 += 16) {
        float4 av = *reinterpret_cast<const float4*>(Ag + k0);
        float4 wv = *reinterpret_cast<const float4*>(Wg + k0);
        __syncthreads();
        As[lr][lc + 0] = av.x; As[lr][lc + 1] = av.y;
        As[lr][lc + 2] = av.z; As[lr][lc + 3] = av.w;
        Ws[lr][lc + 0] = wv.x; Ws[lr][lc + 1] = wv.y;
        Ws[lr][lc + 2] = wv.z; Ws[lr][lc + 3] = wv.w;
        __syncthreads();

        #pragma unroll
        for (int k = 0; k < 16; k++) {
            float a[4], b[4];
            #pragma unroll
            for (int i = 0; i < 4; i++) a[i] = As[ty * 4 + i][k];
            #pragma unroll
            for (int j = 0; j < 4; j++) b[j] = Ws[tx * 4 + j][k];
            #pragma unroll
            for (int i = 0; i < 4; i++)
                #pragma unroll
                for (int j = 0; j < 4; j++)
                    acc[i][j] = fmaf(a[i], b[j], acc[i][j]);
        }
    }

    #pragma unroll
    for (int i = 0; i < 4; i++) {
        const int m = m0 + ty * 4 + i;
        #pragma unroll
        for (int j = 0; j < 4; j++) {
            const int n = n0 + tx * 4 + j;
            float v = acc[i][j];
            if (bias) v += bias[n];
            C[(size_t)m * N + n] = v;
        }
    }
}

__global__ void __launch_bounds__(256) k_gemm_q(const float* __restrict__ x,
                                                const float* __restrict__ Wq)
{
    gemm64(x, Wq, nullptr, g_q);
}

__global__ void __launch_bounds__(256) k_gemm_o(const float* __restrict__ Wu,
                                                const float* __restrict__ bu,
                                                float* __restrict__ out)
{
    gemm64(g_attn, Wu, bu, out);
}

// ---------------------------------------------------------------------------
// Flash-style attention, fp32, Q=K=V=g_q head slice.
// Grid: (T/64, B*H). Block: 256 threads.
// Thread t owns query row i = t/4 within the tile and interleaved dims
// d = dd*4 + (t&3), dd = 0..15. Scores assembled with 2x shfl_xor.
// ---------------------------------------------------------------------------
__global__ void __launch_bounds__(256) k_attn()
{
    __shared__ float Ks[64][65];

    const int tid   = threadIdx.x;
    const int i_loc = tid >> 2;   // 0..63 (query row in tile; also loader row)
    const int dq    = tid & 3;    // dim-quarter
    const int bh    = blockIdx.y; // 0..63
    const int b     = bh >> 4;
    const int h     = bh & 15;
    const int t0    = blockIdx.x << 6;
    const int i_g   = t0 + i_loc;

    const size_t base = (size_t)b * T_ * D_ + (size_t)h * S_;

    // Q row fragment in registers (interleaved dims)
    float q[16];
    #pragma unroll
    for (int dd = 0; dd < 16; dd++)
        q[dd] = g_q[base + (size_t)i_g * D_ + dd * 4 + dq];

    float o[16];
    #pragma unroll
    for (int dd = 0; dd < 16; dd++) o[dd] = 0.f;
    float m = -1e30f, l = 0.f;

    // K-tile loader mapping: 4 threads per key row, 16 consecutive floats each
    const int jr = tid >> 2;
    const int c0 = (tid & 3) * 16;

    for (int j0 = 0; j0 < T_; j0 += 64) {
        const float* kg = &g_q[base + (size_t)(j0 + jr) * D_ + c0];
        float4 v0 = *reinterpret_cast<const float4*>(kg + 0);
        float4 v1 = *reinterpret_cast<const float4*>(kg + 4);
        float4 v2 = *reinterpret_cast<const float4*>(kg + 8);
        float4 v3 = *reinterpret_cast<const float4*>(kg + 12);
        __syncthreads();  // previous tile fully consumed
        Ks[jr][c0 +  0] = v0.x; Ks[jr][c0 +  1] = v0.y;
        Ks[jr][c0 +  2] = v0.z; Ks[jr][c0 +  3] = v0.w;
        Ks[jr][c0 +  4] = v1.x; Ks[jr][c0 +  5] = v1.y;
        Ks[jr][c0 +  6] = v1.z; Ks[jr][c0 +  7] = v1.w;
        Ks[jr][c0 +  8] = v2.x; Ks[jr][c0 +  9] = v2.y;
        Ks[jr][c0 + 10] = v2.z; Ks[jr][c0 + 11] = v2.w;
        Ks[jr][c0 + 12] = v3.x; Ks[jr][c0 + 13] = v3.y;
        Ks[jr][c0 + 14] = v3.z; Ks[jr][c0 + 15] = v3.w;
        __syncthreads();

        // scores for this tile (each thread gets the full row after shuffles)
        float s[64];
        #pragma unroll
        for (int j = 0; j < 64; j++) {
            float d = 0.f;
            #pragma unroll
            for (int dd = 0; dd < 16; dd++)
                d = fmaf(q[dd], Ks[j][dd * 4 + dq], d);
            d += __shfl_xor_sync(0xffffffffu, d, 1);
            d += __shfl_xor_sync(0xffffffffu, d, 2);
            s[j] = d * 0.125f;  // 1/sqrt(64)
        }

        // online softmax update
        float mt = m;
        #pragma unroll
        for (int j = 0; j < 64; j++) mt = fmaxf(mt, s[j]);
        const float corr = __expf(m - mt);
        float lsum = 0.f;
        #pragma unroll
        for (int j = 0; j < 64; j++) {
            s[j] = __expf(s[j] - mt);
            lsum += s[j];
        }
        l = l * corr + lsum;
        #pragma unroll
        for (int dd = 0; dd < 16; dd++) o[dd] *= corr;

        // o += P @ V  (V == K tile)
        #pragma unroll
        for (int j = 0; j < 64; j++)
            #pragma unroll
            for (int dd = 0; dd < 16; dd++)
                o[dd] = fmaf(s[j], Ks[j][dd * 4 + dq], o[dd]);
        m = mt;
    }

    const float inv = 1.f / l;
    #pragma unroll
    for (int dd = 0; dd < 16; dd++)
        g_attn[base + (size_t)i_g * D_ + dd * 4 + dq] = o[dd] * inv;
}

// ---------------------------------------------------------------------------
extern "C" void kernel_launch(void* const* d_in, const int* in_sizes, int n_in,
                              void* d_out, int out_size)
{
    const float* x  = (const float*)d_in[0];
    const float* Wq = (const float*)d_in[1];
    const float* Wu = (const float*)d_in[2];
    const float* bu = (const float*)d_in[3];
    float* out = (float*)d_out;

    dim3 gg(D_ / 64, M_ / 64);   // (16, 128)
    dim3 ga(T_ / 64, B_ * H_);   // (32, 64)

    k_gemm_q<<<gg, 256>>>(x, Wq);
    k_attn<<<ga, 256>>>();
    k_gemm_o<<<gg, 256>>>(Wu, bu, out);
}

// round 2
// speedup vs baseline: 16.4534x; 16.4534x over previous
#include <cuda_runtime.h>

// Problem constants (fixed by the dataset)
#define B_ 4
#define T_ 2048
#define D_ 1024
#define H_ 16
#define S_ 64
#define M_ (B_ * T_)   // 8192 rows

// Scratch (static device allocations are allowed; runtime allocs are not)
__device__ float g_q[(size_t)M_ * D_];     // q = x @ Wq^T, layout (b, t, d)
__device__ float g_attn[(size_t)M_ * D_];  // merged attention output, layout (b, t, d)

#define LDF4(p) (*reinterpret_cast<const float4*>(p))

// ---------------------------------------------------------------------------
// Tiled fp32 GEMM: C[m][n] = sum_k A[m][k] * W[n][k]  (+ optional bias[n])
// A: M x K row-major, W: N x K row-major (torch Linear weight), K=N=1024.
// Tile 64x64, BK=16, 256 threads, 4x4 per thread.
// ---------------------------------------------------------------------------
__device__ __forceinline__ void gemm64(const float* __restrict__ A,
                                       const float* __restrict__ W,
                                       const float* __restrict__ bias,
                                       float* __restrict__ C)
{
    constexpr int K = 1024, N = 1024;
    __shared__ float As[64][17];
    __shared__ float Ws[64][17];

    const int tid = threadIdx.x;
    const int tx = tid & 15;
    const int ty = tid >> 4;
    const int m0 = blockIdx.y << 6;
    const int n0 = blockIdx.x << 6;

    const int lr = tid >> 2;
    const int lc = (tid & 3) << 2;
    const float* Ag = A + (size_t)(m0 + lr) * K + lc;
    const float* Wg = W + (size_t)(n0 + lr) * K + lc;

    float acc[4][4] = {};

    for (int k0 = 0; k0 < K; k0 += 16) {
        float4 av = LDF4(Ag + k0);
        float4 wv = LDF4(Wg + k0);
        __syncthreads();
        As[lr][lc + 0] = av.x; As[lr][lc + 1] = av.y;
        As[lr][lc + 2] = av.z; As[lr][lc + 3] = av.w;
        Ws[lr][lc + 0] = wv.x; Ws[lr][lc + 1] = wv.y;
        Ws[lr][lc + 2] = wv.z; Ws[lr][lc + 3] = wv.w;
        __syncthreads();

        #pragma unroll
        for (int k = 0; k < 16; k++) {
            float a[4], b[4];
            #pragma unroll
            for (int i = 0; i < 4; i++) a[i] = As[ty * 4 + i][k];
            #pragma unroll
            for (int j = 0; j < 4; j++) b[j] = Ws[tx * 4 + j][k];
            #pragma unroll
            for (int i = 0; i < 4; i++)
                #pragma unroll
                for (int j = 0; j < 4; j++)
                    acc[i][j] = fmaf(a[i], b[j], acc[i][j]);
        }
    }

    #pragma unroll
    for (int i = 0; i < 4; i++) {
        const int m = m0 + ty * 4 + i;
        #pragma unroll
        for (int j = 0; j < 4; j++) {
            const int n = n0 + tx * 4 + j;
            float v = acc[i][j];
            if (bias) v += bias[n];
            C[(size_t)m * N + n] = v;
        }
    }
}

__global__ void __launch_bounds__(256) k_gemm_q(const float* __restrict__ x,
                                                const float* __restrict__ Wq)
{
    gemm64(x, Wq, nullptr, g_q);
}

__global__ void __launch_bounds__(256) k_gemm_o(const float* __restrict__ Wu,
                                                const float* __restrict__ bu,
                                                float* __restrict__ out)
{
    gemm64(g_attn, Wu, bu, out);
}

// ---------------------------------------------------------------------------
// Flash-style attention as two register-blocked smem GEMMs per tile.
// Grid: (T/64, B*H), 256 threads, 4x4 per-thread blocking.
//   S = Q K^T   from dim-major tiles Qt/Kt   (conflict-free LDS.128)
//   O += P V    from key-major Pt + natural Kn
// Smem: 4 * 64*68 floats = 68 KB (dynamic, opt-in).
// Thread (tx,ty) owns rows ty*4+i and cols/dims tx*4+j.
// Row softmax state (m,l) reduced across the 16 tx-lanes via shfl_xor.
// ---------------------------------------------------------------------------
#define TSTRIDE 68
#define SMEM_BYTES (4 * 64 * TSTRIDE * 4)

__global__ void __launch_bounds__(256) k_attn()
{
    extern __shared__ float smn[];
    float* Qt = smn;                     // [64][68] dim-major:  Qt[s][row]
    float* Kt = smn + 64 * TSTRIDE;      // [64][68] dim-major:  Kt[s][key]
    float* Kn = smn + 2 * 64 * TSTRIDE;  // [64][68] key-major:  Kn[key][s]
    float* Pt = smn + 3 * 64 * TSTRIDE;  // [64][68] key-major:  Pt[key][row]

    const int tid = threadIdx.x;
    const int tx = tid & 15;
    const int ty = tid >> 4;
    const int bh = blockIdx.y;
    const int b  = bh >> 4;
    const int h  = bh & 15;
    const int t0 = blockIdx.x << 6;
    const size_t base = (size_t)b * T_ * D_ + (size_t)h * S_;

    // Loader mapping: 4 threads per row, 16 consecutive floats each
    const int lr = tid >> 2;          // 0..63
    const int lc = (tid & 3) << 4;    // 0,16,32,48

    // Load Q tile transposed into Qt (dim-major)
    {
        const float* qg = &g_q[base + (size_t)(t0 + lr) * D_ + lc];
        #pragma unroll
        for (int u = 0; u < 4; u++) {
            float4 v = LDF4(qg + 4 * u);
            Qt[(lc + 4*u + 0) * TSTRIDE + lr] = v.x;
            Qt[(lc + 4*u + 1) * TSTRIDE + lr] = v.y;
            Qt[(lc + 4*u + 2) * TSTRIDE + lr] = v.z;
            Qt[(lc + 4*u + 3) * TSTRIDE + lr] = v.w;
        }
    }

    float o[4][4] = {};
    float mrow[4], lrow[4];
    #pragma unroll
    for (int i = 0; i < 4; i++) { mrow[i] = -1e30f; lrow[i] = 0.f; }

    for (int j0 = 0; j0 < T_; j0 += 64) {
        // Stage K tile from gmem into registers
        float4 kv[4];
        const float* kg = &g_q[base + (size_t)(j0 + lr) * D_ + lc];
        #pragma unroll
        for (int u = 0; u < 4; u++) kv[u] = LDF4(kg + 4 * u);

        __syncthreads();  // prev PV done reading Kt/Kn/Pt; Qt visible (iter 0)

        #pragma unroll
        for (int u = 0; u < 4; u++) {
            Kt[(lc + 4*u + 0) * TSTRIDE + lr] = kv[u].x;
            Kt[(lc + 4*u + 1) * TSTRIDE + lr] = kv[u].y;
            Kt[(lc + 4*u + 2) * TSTRIDE + lr] = kv[u].z;
            Kt[(lc + 4*u + 3) * TSTRIDE + lr] = kv[u].w;
            *reinterpret_cast<float4*>(&Kn[lr * TSTRIDE + lc + 4*u]) = kv[u];
        }
        __syncthreads();

        // ---- S = Q K^T ----
        float acc[4][4] = {};
        #pragma unroll 16
        for (int s = 0; s < 64; s++) {
            float4 a = LDF4(&Qt[s * TSTRIDE + ty * 4]);
            float4 bb = LDF4(&Kt[s * TSTRIDE + tx * 4]);
            float av[4] = {a.x, a.y, a.z, a.w};
            float bv[4] = {bb.x, bb.y, bb.z, bb.w};
            #pragma unroll
            for (int i = 0; i < 4; i++)
                #pragma unroll
                for (int j = 0; j < 4; j++)
                    acc[i][j] = fmaf(av[i], bv[j], acc[i][j]);
        }

        // ---- online softmax (per row, reduced over 16 tx-lanes) ----
        #pragma unroll
        for (int i = 0; i < 4; i++) {
            float s0 = acc[i][0] * 0.125f;
            float s1 = acc[i][1] * 0.125f;
            float s2 = acc[i][2] * 0.125f;
            float s3 = acc[i][3] * 0.125f;
            float mx = fmaxf(fmaxf(s0, s1), fmaxf(s2, s3));
            #pragma unroll
            for (int msk = 1; msk < 16; msk <<= 1)
                mx = fmaxf(mx, __shfl_xor_sync(0xffffffffu, mx, msk));
            const float mnew = fmaxf(mrow[i], mx);
            const float corr = __expf(mrow[i] - mnew);
            float p0 = __expf(s0 - mnew);
            float p1 = __expf(s1 - mnew);
            float p2 = __expf(s2 - mnew);
            float p3 = __expf(s3 - mnew);
            float sum = (p0 + p1) + (p2 + p3);
            #pragma unroll
            for (int msk = 1; msk < 16; msk <<= 1)
                sum += __shfl_xor_sync(0xffffffffu, sum, msk);
            lrow[i] = lrow[i] * corr + sum;
            mrow[i] = mnew;
            #pragma unroll
            for (int j = 0; j < 4; j++) o[i][j] *= corr;
            acc[i][0] = p0; acc[i][1] = p1; acc[i][2] = p2; acc[i][3] = p3;
        }

        // store P transposed: Pt[key][row]
        #pragma unroll
        for (int j = 0; j < 4; j++) {
            float4 pv = make_float4(acc[0][j], acc[1][j], acc[2][j], acc[3][j]);
            *reinterpret_cast<float4*>(&Pt[(tx * 4 + j) * TSTRIDE + ty * 4]) = pv;
        }
        __syncthreads();

        // ---- O += P V  (V == K tile, natural layout Kn) ----
        #pragma unroll 16
        for (int j = 0; j < 64; j++) {
            float4 a = LDF4(&Pt[j * TSTRIDE + ty * 4]);
            float4 bb = LDF4(&Kn[j * TSTRIDE + tx * 4]);
            float av[4] = {a.x, a.y, a.z, a.w};
            float bv[4] = {bb.x, bb.y, bb.z, bb.w};
            #pragma unroll
            for (int i = 0; i < 4; i++)
                #pragma unroll
                for (int jj = 0; jj < 4; jj++)
                    o[i][jj] = fmaf(av[i], bv[jj], o[i][jj]);
        }
    }

    // ---- normalize + write out ----
    #pragma unroll
    for (int i = 0; i < 4; i++) {
        const float inv = 1.f / lrow[i];
        float4 ov = make_float4(o[i][0] * inv, o[i][1] * inv,
                                o[i][2] * inv, o[i][3] * inv);
        *reinterpret_cast<float4*>(
            &g_attn[base + (size_t)(t0 + ty * 4 + i) * D_ + tx * 4]) = ov;
    }
}

// ---------------------------------------------------------------------------
extern "C" void kernel_launch(void* const* d_in, const int* in_sizes, int n_in,
                              void* d_out, int out_size)
{
    const float* x  = (const float*)d_in[0];
    const float* Wq = (const float*)d_in[1];
    const float* Wu = (const float*)d_in[2];
    const float* bu = (const float*)d_in[3];
    float* out = (float*)d_out;

    // Opt-in to >48KB dynamic smem (host-side, idempotent, capture-safe)
    cudaFuncSetAttribute(k_attn, cudaFuncAttributeMaxDynamicSharedMemorySize,
                         SMEM_BYTES);

    dim3 gg(D_ / 64, M_ / 64);   // (16, 128)
    dim3 ga(T_ / 64, B_ * H_);   // (32, 64)

    k_gemm_q<<<gg, 256>>>(x, Wq);
    k_attn<<<ga, 256, SMEM_BYTES>>>();
    k_gemm_o<<<gg, 256>>>(Wu, bu, out);
}

// round 5
// speedup vs baseline: 45.9452x; 2.7924x over previous
#include <cuda_runtime.h>
#include <cuda_bf16.h>
#include <cstdint>

#define B_ 4
#define T_ 2048
#define D_ 1024
#define H_ 16
#define S_ 64
#define M_ (B_ * T_)   // 8192

// Scratch (static device globals; runtime allocation is forbidden)
__device__ float g_q  [(size_t)M_ * D_];   // q = x@Wq^T, (b,t,d)
__device__ float g_attn[(size_t)M_ * D_];  // attention out, (b,t,d)

#define LDF4(p) (*reinterpret_cast<const float4*>(p))

__device__ __forceinline__ uint32_t smem_u32(const void* p) {
    uint32_t a;
    asm("{ .reg .u64 t; cvta.to.shared.u64 t, %1; cvt.u32.u64 %0, t; }"
        : "=r"(a) : "l"(p));
    return a;
}
// pack two fp32 -> bf16x2 (element0 = lo_val in low half)
__device__ __forceinline__ uint32_t pk(float lo_val, float hi_val) {
    uint32_t d;
    asm("cvt.rn.bf16x2.f32 %0, %1, %2;" : "=r"(d) : "f"(hi_val), "f"(lo_val));
    return d;
}
__device__ __forceinline__ float bfrnd(float x) {
    return __bfloat162float(__float2bfloat16(x));
}
// float4 -> hi/lo bf16x2 pairs
__device__ __forceinline__ void cvt44(float4 v, uint2& h, uint2& l) {
    h.x = pk(v.x, v.y);
    h.y = pk(v.z, v.w);
    l.x = pk(v.x - bfrnd(v.x), v.y - bfrnd(v.y));
    l.y = pk(v.z - bfrnd(v.z), v.w - bfrnd(v.w));
}

#define LDSM4(r0, r1, r2, r3, a) \
    asm volatile("ldmatrix.sync.aligned.m8n8.x4.shared.b16 {%0,%1,%2,%3}, [%4];" \
        : "=r"(r0), "=r"(r1), "=r"(r2), "=r"(r3) : "r"(a))
#define LDSM4T(r0, r1, r2, r3, a) \
    asm volatile("ldmatrix.sync.aligned.m8n8.x4.trans.shared.b16 {%0,%1,%2,%3}, [%4];" \
        : "=r"(r0), "=r"(r1), "=r"(r2), "=r"(r3) : "r"(a))
#define MMA(c, a0, a1, a2, a3, b0, b1) \
    asm volatile("mma.sync.aligned.m16n8k16.row.col.f32.bf16.bf16.f32 " \
        "{%0,%1,%2,%3}, {%4,%5,%6,%7}, {%8,%9}, {%0,%1,%2,%3};" \
        : "+f"((c)[0]), "+f"((c)[1]), "+f"((c)[2]), "+f"((c)[3]) \
        : "r"(a0), "r"(a1), "r"(a2), "r"(a3), "r"(b0), "r"(b1))

// ---------------------------------------------------------------------------
// Projection GEMM: C[m][n] = sum_k A[m][k]*W[n][k] (+bias), K=N=1024.
// CTA tile 128m x 64n, K-chunk 32. 8 warps: warp (wm,wn) = m32 x n32.
// bf16x3 split for fp32-like accuracy on tensor cores.
// ---------------------------------------------------------------------------
#define GSTR 40   // smem row stride in bf16 elems (80B: conflict-free ldmatrix)

__global__ void __launch_bounds__(256) k_gemm_b(const float* __restrict__ A,
                                                const float* __restrict__ W,
                                                const float* __restrict__ bias,
                                                float* __restrict__ C)
{
    __shared__ __align__(16) __nv_bfloat16 sm[(128 + 128 + 64 + 64) * GSTR];
    __nv_bfloat16* AH = sm;
    __nv_bfloat16* AL = sm + 128 * GSTR;
    __nv_bfloat16* BH = sm + 256 * GSTR;
    __nv_bfloat16* BL = sm + 256 * GSTR + 64 * GSTR;
    const uint32_t sAH = smem_u32(AH), sAL = smem_u32(AL);
    const uint32_t sBH = smem_u32(BH), sBL = smem_u32(BL);

    const int tid = threadIdx.x, lane = tid & 31, wid = tid >> 5;
    const int wm = wid & 3, wn = wid >> 2;
    const int m0 = blockIdx.y << 7, n0 = blockIdx.x << 6;

    // loaders: A rows (2 thr/row, 16 floats each), W rows (4 thr/row, 8 floats)
    const int arow = tid >> 1, ac0 = (tid & 1) << 4;
    const int wrow = tid >> 2, wc0 = (tid & 3) << 3;
    const float* Ag = A + (size_t)(m0 + arow) * 1024 + ac0;
    const float* Wg = W + (size_t)(n0 + wrow) * 1024 + wc0;

    float4 va[4], vw[2];
    #pragma unroll
    for (int u = 0; u < 4; u++) va[u] = LDF4(Ag + 4 * u);
    vw[0] = LDF4(Wg);
    vw[1] = LDF4(Wg + 4);

    float acc[2][4][4] = {};

    for (int k0 = 0; k0 < 1024; k0 += 32) {
        __syncthreads();
        #pragma unroll
        for (int u = 0; u < 4; u++) {
            uint2 h, l;
            cvt44(va[u], h, l);
            const int off = arow * GSTR + ac0 + 4 * u;
            *reinterpret_cast<uint2*>(&AH[off]) = h;
            *reinterpret_cast<uint2*>(&AL[off]) = l;
        }
        #pragma unroll
        for (int u = 0; u < 2; u++) {
            uint2 h, l;
            cvt44(vw[u], h, l);
            const int off = wrow * GSTR + wc0 + 4 * u;
            *reinterpret_cast<uint2*>(&BH[off]) = h;
            *reinterpret_cast<uint2*>(&BL[off]) = l;
        }
        __syncthreads();

        if (k0 < 1024 - 32) {
            #pragma unroll
            for (int u = 0; u < 4; u++) va[u] = LDF4(Ag + k0 + 32 + 4 * u);
            vw[0] = LDF4(Wg + k0 + 32);
            vw[1] = LDF4(Wg + k0 + 36);
        }

        #pragma unroll
        for (int kk = 0; kk < 32; kk += 16) {
            uint32_t ah[2][4], al[2][4];
            #pragma unroll
            for (int mt = 0; mt < 2; mt++) {
                const int r = wm * 32 + mt * 16 + (lane & 15);
                const int c = kk + ((lane >> 4) << 3);
                const uint32_t off = (uint32_t)(r * GSTR + c) * 2;
                LDSM4(ah[mt][0], ah[mt][1], ah[mt][2], ah[mt][3], sAH + off);
                LDSM4(al[mt][0], al[mt][1], al[mt][2], al[mt][3], sAL + off);
            }
            uint32_t bh[4][2], bl[4][2];
            #pragma unroll
            for (int p = 0; p < 2; p++) {
                const int r = wn * 32 + p * 16 + (lane & 7) + ((lane >> 4) << 3);
                const int c = kk + (((lane >> 3) & 1) << 3);
                const uint32_t off = (uint32_t)(r * GSTR + c) * 2;
                LDSM4(bh[2*p][0], bh[2*p][1], bh[2*p+1][0], bh[2*p+1][1], sBH + off);
                LDSM4(bl[2*p][0], bl[2*p][1], bl[2*p+1][0], bl[2*p+1][1], sBL + off);
            }
            #pragma unroll
            for (int mt = 0; mt < 2; mt++)
                #pragma unroll
                for (int nt = 0; nt < 4; nt++) {
                    MMA(acc[mt][nt], ah[mt][0], ah[mt][1], ah[mt][2], ah[mt][3],
                        bh[nt][0], bh[nt][1]);
                    MMA(acc[mt][nt], ah[mt][0], ah[mt][1], ah[mt][2], ah[mt][3],
                        bl[nt][0], bl[nt][1]);
                    MMA(acc[mt][nt], al[mt][0], al[mt][1], al[mt][2], al[mt][3],
                        bh[nt][0], bh[nt][1]);
                }
        }
    }

    // epilogue
    #pragma unroll
    for (int mt = 0; mt < 2; mt++) {
        const int r = m0 + wm * 32 + mt * 16 + (lane >> 2);
        #pragma unroll
        for (int nt = 0; nt < 4; nt++) {
            const int c = n0 + wn * 32 + nt * 8 + 2 * (lane & 3);
            float2 v0 = make_float2(acc[mt][nt][0], acc[mt][nt][1]);
            float2 v1 = make_float2(acc[mt][nt][2], acc[mt][nt][3]);
            if (bias) {
                const float b0 = bias[c], b1 = bias[c + 1];
                v0.x += b0; v0.y += b1;
                v1.x += b0; v1.y += b1;
            }
            *reinterpret_cast<float2*>(&C[(size_t)r * 1024 + c]) = v0;
            *reinterpret_cast<float2*>(&C[(size_t)(r + 8) * 1024 + c]) = v1;
        }
    }
}

// ---------------------------------------------------------------------------
// Flash attention, bf16x3 mma.sync. 1 CTA per (bh, 128 q-rows), 256 threads.
// Warp w owns q-rows [w*16, w*16+16). S-fragments stay in registers through
// softmax and are re-packed as A-fragments for PV (C-frag layout == A-frag).
// V is read from the K smem tiles via ldmatrix.trans.
// ---------------------------------------------------------------------------
#define ASTR 72   // smem row stride in bf16 elems (144B: conflict-free ldmatrix)
#define AT_SMEM (4 * 128 * ASTR * 2)   // QH,QL,KH,KL = 73728 B

__global__ void __launch_bounds__(256) k_attn_b()
{
    extern __shared__ __nv_bfloat16 smb[];
    __nv_bfloat16* QH = smb;
    __nv_bfloat16* QL = smb + 128 * ASTR;
    __nv_bfloat16* KH = smb + 2 * 128 * ASTR;
    __nv_bfloat16* KL = smb + 3 * 128 * ASTR;
    const uint32_t sQH = smem_u32(QH), sQL = smem_u32(QL);
    const uint32_t sKH = smem_u32(KH), sKL = smem_u32(KL);

    const int tid = threadIdx.x, lane = tid & 31, wid = tid >> 5;
    const int bh = blockIdx.y;
    const int b = bh >> 4, h = bh & 15;
    const int t0 = blockIdx.x << 7;
    const size_t qbase = (size_t)b * T_ * D_ + (size_t)h * S_;

    // loader: 2 threads per row, 32 floats each
    const int row = tid >> 1, c0 = (tid & 1) << 5;

    // Q tile -> smem (hi/lo)
    {
        const float* qg = g_q + qbase + (size_t)(t0 + row) * D_ + c0;
        #pragma unroll
        for (int u = 0; u < 8; u++) {
            float4 v = LDF4(qg + 4 * u);
            uint2 hh, ll;
            cvt44(v, hh, ll);
            const int off = row * ASTR + c0 + 4 * u;
            *reinterpret_cast<uint2*>(&QH[off]) = hh;
            *reinterpret_cast<uint2*>(&QL[off]) = ll;
        }
    }

    // prefetch first K tile
    float4 kv[8];
    {
        const float* kg = g_q + qbase + (size_t)row * D_ + c0;
        #pragma unroll
        for (int u = 0; u < 8; u++) kv[u] = LDF4(kg + 4 * u);
    }

    float oacc[8][4] = {};
    float mrow[2] = {-1e30f, -1e30f};
    float lrow[2] = {0.f, 0.f};

    for (int j0 = 0; j0 < T_; j0 += 128) {
        __syncthreads();   // prior consumers done with K smem (and Q visible)
        #pragma unroll
        for (int u = 0; u < 8; u++) {
            uint2 hh, ll;
            cvt44(kv[u], hh, ll);
            const int off = row * ASTR + c0 + 4 * u;
            *reinterpret_cast<uint2*>(&KH[off]) = hh;
            *reinterpret_cast<uint2*>(&KL[off]) = ll;
        }
        __syncthreads();

        // ---- S = Q K^T ----
        float sacc[16][4] = {};
        #pragma unroll
        for (int kk = 0; kk < 4; kk++) {
            const int ar = wid * 16 + (lane & 15);
            const int acl = kk * 16 + ((lane >> 4) << 3);
            const uint32_t aoff = (uint32_t)(ar * ASTR + acl) * 2;
            uint32_t ah[4], al[4];
            LDSM4(ah[0], ah[1], ah[2], ah[3], sQH + aoff);
            LDSM4(al[0], al[1], al[2], al[3], sQL + aoff);
            #pragma unroll
            for (int p = 0; p < 8; p++) {
                const int br = p * 16 + (lane & 7) + ((lane >> 4) << 3);
                const int bc = kk * 16 + (((lane >> 3) & 1) << 3);
                const uint32_t boff = (uint32_t)(br * ASTR + bc) * 2;
                uint32_t bh[4], bl[4];
                LDSM4(bh[0], bh[1], bh[2], bh[3], sKH + boff);
                LDSM4(bl[0], bl[1], bl[2], bl[3], sKL + boff);
                MMA(sacc[2*p],   ah[0], ah[1], ah[2], ah[3], bh[0], bh[1]);
                MMA(sacc[2*p],   ah[0], ah[1], ah[2], ah[3], bl[0], bl[1]);
                MMA(sacc[2*p],   al[0], al[1], al[2], al[3], bh[0], bh[1]);
                MMA(sacc[2*p+1], ah[0], ah[1], ah[2], ah[3], bh[2], bh[3]);
                MMA(sacc[2*p+1], ah[0], ah[1], ah[2], ah[3], bl[2], bl[3]);
                MMA(sacc[2*p+1], al[0], al[1], al[2], al[3], bh[2], bh[3]);
            }
        }

        // prefetch next K tile while softmax/PV run
        if (j0 + 128 < T_) {
            const float* kg = g_q + qbase + (size_t)(j0 + 128 + row) * D_ + c0;
            #pragma unroll
            for (int u = 0; u < 8; u++) kv[u] = LDF4(kg + 4 * u);
        }

        // ---- online softmax (rows: lane/4 and lane/4+8; quad reductions) ----
        float mx0 = -1e30f, mx1 = -1e30f;
        #pragma unroll
        for (int nt = 0; nt < 16; nt++) {
            mx0 = fmaxf(mx0, fmaxf(sacc[nt][0], sacc[nt][1]));
            mx1 = fmaxf(mx1, fmaxf(sacc[nt][2], sacc[nt][3]));
        }
        mx0 = fmaxf(mx0, __shfl_xor_sync(0xffffffffu, mx0, 1));
        mx0 = fmaxf(mx0, __shfl_xor_sync(0xffffffffu, mx0, 2));
        mx1 = fmaxf(mx1, __shfl_xor_sync(0xffffffffu, mx1, 1));
        mx1 = fmaxf(mx1, __shfl_xor_sync(0xffffffffu, mx1, 2));
        const float mn0 = fmaxf(mrow[0], 0.125f * mx0);
        const float mn1 = fmaxf(mrow[1], 0.125f * mx1);
        const float corr0 = __expf(mrow[0] - mn0);
        const float corr1 = __expf(mrow[1] - mn1);
        float sum0 = 0.f, sum1 = 0.f;
        #pragma unroll
        for (int nt = 0; nt < 16; nt++) {
            sacc[nt][0] = __expf(fmaf(0.125f, sacc[nt][0], -mn0));
            sacc[nt][1] = __expf(fmaf(0.125f, sacc[nt][1], -mn0));
            sacc[nt][2] = __expf(fmaf(0.125f, sacc[nt][2], -mn1));
            sacc[nt][3] = __expf(fmaf(0.125f, sacc[nt][3], -mn1));
            sum0 += sacc[nt][0] + sacc[nt][1];
            sum1 += sacc[nt][2] + sacc[nt][3];
        }
        sum0 += __shfl_xor_sync(0xffffffffu, sum0, 1);
        sum0 += __shfl_xor_sync(0xffffffffu, sum0, 2);
        sum1 += __shfl_xor_sync(0xffffffffu, sum1, 1);
        sum1 += __shfl_xor_sync(0xffffffffu, sum1, 2);
        lrow[0] = lrow[0] * corr0 + sum0;
        lrow[1] = lrow[1] * corr1 + sum1;
        mrow[0] = mn0;
        mrow[1] = mn1;
        #pragma unroll
        for (int dt = 0; dt < 8; dt++) {
            oacc[dt][0] *= corr0; oacc[dt][1] *= corr0;
            oacc[dt][2] *= corr1; oacc[dt][3] *= corr1;
        }

        // ---- O += P V  (P from registers; V via ldmatrix.trans on K smem) ----
        #pragma unroll
        for (int kk = 0; kk < 8; kk++) {
            const float p00 = sacc[2*kk][0],   p01 = sacc[2*kk][1];
            const float p02 = sacc[2*kk][2],   p03 = sacc[2*kk][3];
            const float p10 = sacc[2*kk+1][0], p11 = sacc[2*kk+1][1];
            const float p12 = sacc[2*kk+1][2], p13 = sacc[2*kk+1][3];
            const uint32_t ah0 = pk(p00, p01), ah1 = pk(p02, p03);
            const uint32_t ah2 = pk(p10, p11), ah3 = pk(p12, p13);
            const uint32_t al0 = pk(p00 - bfrnd(p00), p01 - bfrnd(p01));
            const uint32_t al1 = pk(p02 - bfrnd(p02), p03 - bfrnd(p03));
            const uint32_t al2 = pk(p10 - bfrnd(p10), p11 - bfrnd(p11));
            const uint32_t al3 = pk(p12 - bfrnd(p12), p13 - bfrnd(p13));
            #pragma unroll
            for (int dp = 0; dp < 4; dp++) {   // FIX: full head dim (8 n8-tiles)
                const int vr = kk * 16 + (lane & 7) + (((lane >> 3) & 1) << 3);
                const int vc = dp * 16 + ((lane >> 4) << 3);
                const uint32_t voff = (uint32_t)(vr * ASTR + vc) * 2;
                uint32_t bh[4], bl[4];
                LDSM4T(bh[0], bh[1], bh[2], bh[3], sKH + voff);
                LDSM4T(bl[0], bl[1], bl[2], bl[3], sKL + voff);
                MMA(oacc[2*dp],   ah0, ah1, ah2, ah3, bh[0], bh[1]);
                MMA(oacc[2*dp],   ah0, ah1, ah2, ah3, bl[0], bl[1]);
                MMA(oacc[2*dp],   al0, al1, al2, al3, bh[0], bh[1]);
                MMA(oacc[2*dp+1], ah0, ah1, ah2, ah3, bh[2], bh[3]);
                MMA(oacc[2*dp+1], ah0, ah1, ah2, ah3, bl[2], bl[3]);
                MMA(oacc[2*dp+1], al0, al1, al2, al3, bh[2], bh[3]);
            }
        }
    }

    // ---- epilogue: normalize + write ----
    const float inv0 = 1.f / lrow[0];
    const float inv1 = 1.f / lrow[1];
    const int r0 = t0 + wid * 16 + (lane >> 2);
    #pragma unroll
    for (int dt = 0; dt < 8; dt++) {
        const int c = dt * 8 + 2 * (lane & 3);
        float2 v0 = make_float2(oacc[dt][0] * inv0, oacc[dt][1] * inv0);
        float2 v1 = make_float2(oacc[dt][2] * inv1, oacc[dt][3] * inv1);
        *reinterpret_cast<float2*>(&g_attn[qbase + (size_t)r0 * D_ + c]) = v0;
        *reinterpret_cast<float2*>(&g_attn[qbase + (size_t)(r0 + 8) * D_ + c]) = v1;
    }
}

// ---------------------------------------------------------------------------
extern "C" void kernel_launch(void* const* d_in, const int* in_sizes, int n_in,
                              void* d_out, int out_size)
{
    const float* x  = (const float*)d_in[0];
    const float* Wq = (const float*)d_in[1];
    const float* Wu = (const float*)d_in[2];
    const float* bu = (const float*)d_in[3];
    float* out = (float*)d_out;

    cudaFuncSetAttribute(k_attn_b, cudaFuncAttributeMaxDynamicSharedMemorySize,
                         AT_SMEM);

    float* gq; cudaGetSymbolAddress((void**)&gq, g_q);
    float* ga; cudaGetSymbolAddress((void**)&ga, g_attn);

    dim3 gg(D_ / 64, M_ / 128);    // (16, 64)
    dim3 gat(T_ / 128, B_ * H_);   // (16, 64)

    k_gemm_b<<<gg, 256>>>(x, Wq, nullptr, gq);
    k_attn_b<<<gat, 256, AT_SMEM>>>();
    k_gemm_b<<<gg, 256>>>(ga, Wu, bu, out);
}

// round 6
// speedup vs baseline: 53.2094x; 1.1581x over previous
#include <cuda_runtime.h>
#include <cuda_bf16.h>
#include <cstdint>

#define B_ 4
#define T_ 2048
#define D_ 1024
#define H_ 16
#define S_ 64
#define M_ (B_ * T_)   // 8192

// Pre-split bf16 hi/lo scratch (static device globals; no runtime alloc)
__device__ __nv_bfloat16 g_qh[(size_t)M_ * D_];
__device__ __nv_bfloat16 g_ql[(size_t)M_ * D_];
__device__ __nv_bfloat16 g_ah[(size_t)M_ * D_];
__device__ __nv_bfloat16 g_al[(size_t)M_ * D_];

#define LDF4(p) (*reinterpret_cast<const float4*>(p))

__device__ __forceinline__ uint32_t smem_u32(const void* p) {
    uint32_t a;
    asm("{ .reg .u64 t; cvta.to.shared.u64 t, %1; cvt.u32.u64 %0, t; }"
        : "=r"(a) : "l"(p));
    return a;
}
__device__ __forceinline__ uint32_t pk(float lo_val, float hi_val) {
    uint32_t d;
    asm("cvt.rn.bf16x2.f32 %0, %1, %2;" : "=r"(d) : "f"(hi_val), "f"(lo_val));
    return d;
}
__device__ __forceinline__ float bfrnd(float x) {
    return __bfloat162float(__float2bfloat16(x));
}
__device__ __forceinline__ void cvt44(float4 v, uint2& h, uint2& l) {
    h.x = pk(v.x, v.y);
    h.y = pk(v.z, v.w);
    l.x = pk(v.x - bfrnd(v.x), v.y - bfrnd(v.y));
    l.y = pk(v.z - bfrnd(v.z), v.w - bfrnd(v.w));
}
__device__ __forceinline__ void cpa16(uint32_t d, const __nv_bfloat16* s) {
    asm volatile("cp.async.ca.shared.global [%0], [%1], 16;"
                 :: "r"(d), "l"((size_t)__cvta_generic_to_global(s)));
}
#define CPCOMMIT() asm volatile("cp.async.commit_group;")
#define CPWAIT0()  asm volatile("cp.async.wait_group 0;")
#define CPWAIT1()  asm volatile("cp.async.wait_group 1;")

#define LDSM4(r0, r1, r2, r3, a) \
    asm volatile("ldmatrix.sync.aligned.m8n8.x4.shared.b16 {%0,%1,%2,%3}, [%4];" \
        : "=r"(r0), "=r"(r1), "=r"(r2), "=r"(r3) : "r"(a))
#define LDSM4T(r0, r1, r2, r3, a) \
    asm volatile("ldmatrix.sync.aligned.m8n8.x4.trans.shared.b16 {%0,%1,%2,%3}, [%4];" \
        : "=r"(r0), "=r"(r1), "=r"(r2), "=r"(r3) : "r"(a))
#define MMA(c, a0, a1, a2, a3, b0, b1) \
    asm volatile("mma.sync.aligned.m16n8k16.row.col.f32.bf16.bf16.f32 " \
        "{%0,%1,%2,%3}, {%4,%5,%6,%7}, {%8,%9}, {%0,%1,%2,%3};" \
        : "+f"((c)[0]), "+f"((c)[1]), "+f"((c)[2]), "+f"((c)[3]) \
        : "r"(a0), "r"(a1), "r"(a2), "r"(a3), "r"(b0), "r"(b1))

// ---------------------------------------------------------------------------
// q-proj GEMM: g_qh/g_ql[m][n] = split( sum_k x[m][k]*Wq[n][k] ).
// CTA 128m x 64n, K-chunk 32, 8 warps (m32 x n32 each). bf16x3.
// ---------------------------------------------------------------------------
#define GSTR 40

__global__ void __launch_bounds__(256) k_gemm_q(const float* __restrict__ A,
                                                const float* __restrict__ W)
{
    __shared__ __align__(16) __nv_bfloat16 sm[(128 + 128 + 64 + 64) * GSTR];
    __nv_bfloat16* AH = sm;
    __nv_bfloat16* AL = sm + 128 * GSTR;
    __nv_bfloat16* BH = sm + 256 * GSTR;
    __nv_bfloat16* BL = sm + 256 * GSTR + 64 * GSTR;
    const uint32_t sAH = smem_u32(AH), sAL = smem_u32(AL);
    const uint32_t sBH = smem_u32(BH), sBL = smem_u32(BL);

    const int tid = threadIdx.x, lane = tid & 31, wid = tid >> 5;
    const int wm = wid & 3, wn = wid >> 2;
    const int m0 = blockIdx.y << 7, n0 = blockIdx.x << 6;

    const int arow = tid >> 1, ac0 = (tid & 1) << 4;
    const int wrow = tid >> 2, wc0 = (tid & 3) << 3;
    const float* Ag = A + (size_t)(m0 + arow) * 1024 + ac0;
    const float* Wg = W + (size_t)(n0 + wrow) * 1024 + wc0;

    float4 va[4], vw[2];
    #pragma unroll
    for (int u = 0; u < 4; u++) va[u] = LDF4(Ag + 4 * u);
    vw[0] = LDF4(Wg);
    vw[1] = LDF4(Wg + 4);

    float acc[2][4][4] = {};

    for (int k0 = 0; k0 < 1024; k0 += 32) {
        __syncthreads();
        #pragma unroll
        for (int u = 0; u < 4; u++) {
            uint2 h, l;
            cvt44(va[u], h, l);
            const int off = arow * GSTR + ac0 + 4 * u;
            *reinterpret_cast<uint2*>(&AH[off]) = h;
            *reinterpret_cast<uint2*>(&AL[off]) = l;
        }
        #pragma unroll
        for (int u = 0; u < 2; u++) {
            uint2 h, l;
            cvt44(vw[u], h, l);
            const int off = wrow * GSTR + wc0 + 4 * u;
            *reinterpret_cast<uint2*>(&BH[off]) = h;
            *reinterpret_cast<uint2*>(&BL[off]) = l;
        }
        __syncthreads();

        if (k0 < 1024 - 32) {
            #pragma unroll
            for (int u = 0; u < 4; u++) va[u] = LDF4(Ag + k0 + 32 + 4 * u);
            vw[0] = LDF4(Wg + k0 + 32);
            vw[1] = LDF4(Wg + k0 + 36);
        }

        #pragma unroll
        for (int kk = 0; kk < 32; kk += 16) {
            uint32_t ah[2][4], al[2][4];
            #pragma unroll
            for (int mt = 0; mt < 2; mt++) {
                const int r = wm * 32 + mt * 16 + (lane & 15);
                const int c = kk + ((lane >> 4) << 3);
                const uint32_t off = (uint32_t)(r * GSTR + c) * 2;
                LDSM4(ah[mt][0], ah[mt][1], ah[mt][2], ah[mt][3], sAH + off);
                LDSM4(al[mt][0], al[mt][1], al[mt][2], al[mt][3], sAL + off);
            }
            uint32_t bh[4][2], bl[4][2];
            #pragma unroll
            for (int p = 0; p < 2; p++) {
                const int r = wn * 32 + p * 16 + (lane & 7) + ((lane >> 4) << 3);
                const int c = kk + (((lane >> 3) & 1) << 3);
                const uint32_t off = (uint32_t)(r * GSTR + c) * 2;
                LDSM4(bh[2*p][0], bh[2*p][1], bh[2*p+1][0], bh[2*p+1][1], sBH + off);
                LDSM4(bl[2*p][0], bl[2*p][1], bl[2*p+1][0], bl[2*p+1][1], sBL + off);
            }
            #pragma unroll
            for (int mt = 0; mt < 2; mt++)
                #pragma unroll
                for (int nt = 0; nt < 4; nt++) {
                    MMA(acc[mt][nt], ah[mt][0], ah[mt][1], ah[mt][2], ah[mt][3],
                        bh[nt][0], bh[nt][1]);
                    MMA(acc[mt][nt], ah[mt][0], ah[mt][1], ah[mt][2], ah[mt][3],
                        bl[nt][0], bl[nt][1]);
                    MMA(acc[mt][nt], al[mt][0], al[mt][1], al[mt][2], al[mt][3],
                        bh[nt][0], bh[nt][1]);
                }
        }
    }

    // epilogue: split to bf16 hi/lo
    #pragma unroll
    for (int mt = 0; mt < 2; mt++) {
        const int r = m0 + wm * 32 + mt * 16 + (lane >> 2);
        #pragma unroll
        for (int nt = 0; nt < 4; nt++) {
            const int c = n0 + wn * 32 + nt * 8 + 2 * (lane & 3);
            const float a0 = acc[mt][nt][0], a1 = acc[mt][nt][1];
            const float a2 = acc[mt][nt][2], a3 = acc[mt][nt][3];
            const size_t ia = (size_t)r * 1024 + c;
            const size_t ib = (size_t)(r + 8) * 1024 + c;
            *reinterpret_cast<uint32_t*>(&g_qh[ia]) = pk(a0, a1);
            *reinterpret_cast<uint32_t*>(&g_ql[ia]) = pk(a0 - bfrnd(a0), a1 - bfrnd(a1));
            *reinterpret_cast<uint32_t*>(&g_qh[ib]) = pk(a2, a3);
            *reinterpret_cast<uint32_t*>(&g_ql[ib]) = pk(a2 - bfrnd(a2), a3 - bfrnd(a3));
        }
    }
}

// ---------------------------------------------------------------------------
// o-proj GEMM: out[m][n] = sum_k (g_ah+g_al)[m][k]*Wu[n][k] + bu[n].
// A-side reads pre-split bf16 (pure copies to smem).
// ---------------------------------------------------------------------------
__global__ void __launch_bounds__(256) k_gemm_o(const float* __restrict__ W,
                                                const float* __restrict__ bias,
                                                float* __restrict__ C)
{
    __shared__ __align__(16) __nv_bfloat16 sm[(128 + 128 + 64 + 64) * GSTR];
    __nv_bfloat16* AH = sm;
    __nv_bfloat16* AL = sm + 128 * GSTR;
    __nv_bfloat16* BH = sm + 256 * GSTR;
    __nv_bfloat16* BL = sm + 256 * GSTR + 64 * GSTR;
    const uint32_t sAH = smem_u32(AH), sAL = smem_u32(AL);
    const uint32_t sBH = smem_u32(BH), sBL = smem_u32(BL);

    const int tid = threadIdx.x, lane = tid & 31, wid = tid >> 5;
    const int wm = wid & 3, wn = wid >> 2;
    const int m0 = blockIdx.y << 7, n0 = blockIdx.x << 6;

    const int arow = tid >> 1, ac0 = (tid & 1) << 4;
    const int wrow = tid >> 2, wc0 = (tid & 3) << 3;
    const size_t abase = (size_t)(m0 + arow) * 1024 + ac0;
    const float* Wg = W + (size_t)(n0 + wrow) * 1024 + wc0;

    uint4 ha[2], la[2];
    float4 vw[2];
    ha[0] = *reinterpret_cast<const uint4*>(g_ah + abase);
    ha[1] = *reinterpret_cast<const uint4*>(g_ah + abase + 8);
    la[0] = *reinterpret_cast<const uint4*>(g_al + abase);
    la[1] = *reinterpret_cast<const uint4*>(g_al + abase + 8);
    vw[0] = LDF4(Wg);
    vw[1] = LDF4(Wg + 4);

    float acc[2][4][4] = {};

    for (int k0 = 0; k0 < 1024; k0 += 32) {
        __syncthreads();
        {
            const int off = arow * GSTR + ac0;
            *reinterpret_cast<uint4*>(&AH[off]) = ha[0];
            *reinterpret_cast<uint4*>(&AH[off + 8]) = ha[1];
            *reinterpret_cast<uint4*>(&AL[off]) = la[0];
            *reinterpret_cast<uint4*>(&AL[off + 8]) = la[1];
        }
        #pragma unroll
        for (int u = 0; u < 2; u++) {
            uint2 h, l;
            cvt44(vw[u], h, l);
            const int off = wrow * GSTR + wc0 + 4 * u;
            *reinterpret_cast<uint2*>(&BH[off]) = h;
            *reinterpret_cast<uint2*>(&BL[off]) = l;
        }
        __syncthreads();

        if (k0 < 1024 - 32) {
            ha[0] = *reinterpret_cast<const uint4*>(g_ah + abase + k0 + 32);
            ha[1] = *reinterpret_cast<const uint4*>(g_ah + abase + k0 + 40);
            la[0] = *reinterpret_cast<const uint4*>(g_al + abase + k0 + 32);
            la[1] = *reinterpret_cast<const uint4*>(g_al + abase + k0 + 40);
            vw[0] = LDF4(Wg + k0 + 32);
            vw[1] = LDF4(Wg + k0 + 36);
        }

        #pragma unroll
        for (int kk = 0; kk < 32; kk += 16) {
            uint32_t ah[2][4], al[2][4];
            #pragma unroll
            for (int mt = 0; mt < 2; mt++) {
                const int r = wm * 32 + mt * 16 + (lane & 15);
                const int c = kk + ((lane >> 4) << 3);
                const uint32_t off = (uint32_t)(r * GSTR + c) * 2;
                LDSM4(ah[mt][0], ah[mt][1], ah[mt][2], ah[mt][3], sAH + off);
                LDSM4(al[mt][0], al[mt][1], al[mt][2], al[mt][3], sAL + off);
            }
            uint32_t bh[4][2], bl[4][2];
            #pragma unroll
            for (int p = 0; p < 2; p++) {
                const int r = wn * 32 + p * 16 + (lane & 7) + ((lane >> 4) << 3);
                const int c = kk + (((lane >> 3) & 1) << 3);
                const uint32_t off = (uint32_t)(r * GSTR + c) * 2;
                LDSM4(bh[2*p][0], bh[2*p][1], bh[2*p+1][0], bh[2*p+1][1], sBH + off);
                LDSM4(bl[2*p][0], bl[2*p][1], bl[2*p+1][0], bl[2*p+1][1], sBL + off);
            }
            #pragma unroll
            for (int mt = 0; mt < 2; mt++)
                #pragma unroll
                for (int nt = 0; nt < 4; nt++) {
                    MMA(acc[mt][nt], ah[mt][0], ah[mt][1], ah[mt][2], ah[mt][3],
                        bh[nt][0], bh[nt][1]);
                    MMA(acc[mt][nt], ah[mt][0], ah[mt][1], ah[mt][2], ah[mt][3],
                        bl[nt][0], bl[nt][1]);
                    MMA(acc[mt][nt], al[mt][0], al[mt][1], al[mt][2], al[mt][3],
                        bh[nt][0], bh[nt][1]);
                }
        }
    }

    #pragma unroll
    for (int mt = 0; mt < 2; mt++) {
        const int r = m0 + wm * 32 + mt * 16 + (lane >> 2);
        #pragma unroll
        for (int nt = 0; nt < 4; nt++) {
            const int c = n0 + wn * 32 + nt * 8 + 2 * (lane & 3);
            const float b0 = bias[c], b1 = bias[c + 1];
            float2 v0 = make_float2(acc[mt][nt][0] + b0, acc[mt][nt][1] + b1);
            float2 v1 = make_float2(acc[mt][nt][2] + b0, acc[mt][nt][3] + b1);
            *reinterpret_cast<float2*>(&C[(size_t)r * 1024 + c]) = v0;
            *reinterpret_cast<float2*>(&C[(size_t)(r + 8) * 1024 + c]) = v1;
        }
    }
}

// ---------------------------------------------------------------------------
// Flash attention v2: 128 threads, 4 warps, warp = m32. Key tile = 64,
// cp.async double-buffered. Q fragments cached in registers for all tiles.
// smem stages: KH0 | KL0 | KH1 | KL1, each 64 x 72 bf16.
// ---------------------------------------------------------------------------
#define ASTR 72

__global__ void __launch_bounds__(128) k_attn2()
{
    __shared__ __align__(16) __nv_bfloat16 smk[4 * 64 * ASTR];  // 36864 B
    const uint32_t sb = smem_u32(smk);
    const uint32_t sH[2] = {sb, sb + 18432u};
    const uint32_t sL[2] = {sb + 9216u, sb + 27648u};

    const int tid = threadIdx.x, lane = tid & 31, wid = tid >> 5;
    const int bh = blockIdx.y, b = bh >> 4, h = bh & 15;
    const int t0 = blockIdx.x << 7;
    const size_t qbase = (size_t)b * T_ * D_ + (size_t)h * S_;

    // Q rows [t0, t0+128): rows 0-63 -> stage0, 64-127 -> stage1
    {
        const int stg = tid >> 6, qlr = tid & 63;
        const size_t off = qbase + (size_t)(t0 + tid) * D_;
        const uint32_t dh = sH[stg] + (uint32_t)qlr * 144u;
        const uint32_t dl = sL[stg] + (uint32_t)qlr * 144u;
        #pragma unroll
        for (int i = 0; i < 8; i++) {
            cpa16(dh + i * 16, g_qh + off + i * 8);
            cpa16(dl + i * 16, g_ql + off + i * 8);
        }
        CPCOMMIT();
    }
    CPWAIT0();
    __syncthreads();

    // Q fragments -> registers (reused for all 32 key tiles)
    uint32_t qh[2][4][4], ql[2][4][4];
    {
        const int stg = wid >> 1, rb = (wid & 1) << 5;
        #pragma unroll
        for (int mt = 0; mt < 2; mt++)
            #pragma unroll
            for (int kk = 0; kk < 4; kk++) {
                const int ar = rb + mt * 16 + (lane & 15);
                const int ac = kk * 16 + ((lane >> 4) << 3);
                const uint32_t o = (uint32_t)(ar * ASTR + ac) * 2;
                LDSM4(qh[mt][kk][0], qh[mt][kk][1], qh[mt][kk][2], qh[mt][kk][3],
                      sH[stg] + o);
                LDSM4(ql[mt][kk][0], ql[mt][kk][1], ql[mt][kk][2], ql[mt][kk][3],
                      sL[stg] + o);
            }
    }
    __syncthreads();

    float oacc[2][8][4] = {};
    float mr[2][2] = {{-1e30f, -1e30f}, {-1e30f, -1e30f}};
    float lsum[2][2] = {};

    const int krow = tid >> 1, kseg = tid & 1;
    // prime pipeline: tiles 0, 1
    #pragma unroll
    for (int t = 0; t < 2; t++) {
        const size_t off = qbase + (size_t)(t * 64 + krow) * D_ + kseg * 32;
        const uint32_t dh = sH[t] + (uint32_t)(krow * 144 + kseg * 64);
        const uint32_t dl = sL[t] + (uint32_t)(krow * 144 + kseg * 64);
        #pragma unroll
        for (int i = 0; i < 4; i++) {
            cpa16(dh + i * 16, g_qh + off + i * 8);
            cpa16(dl + i * 16, g_ql + off + i * 8);
        }
        CPCOMMIT();
    }

    for (int t = 0; t < 32; t++) {
        const int st = t & 1;
        if (t == 31) { CPWAIT0(); } else { CPWAIT1(); }
        __syncthreads();

        // ---- S = Q K^T  (m32 x 64 keys) ----
        float sacc[2][8][4] = {};
        #pragma unroll
        for (int kk = 0; kk < 4; kk++)
            #pragma unroll
            for (int p = 0; p < 4; p++) {
                const int br = p * 16 + (lane & 7) + ((lane >> 4) << 3);
                const int bc = kk * 16 + (((lane >> 3) & 1) << 3);
                const uint32_t o = (uint32_t)(br * ASTR + bc) * 2;
                uint32_t bh4[4], bl4[4];
                LDSM4(bh4[0], bh4[1], bh4[2], bh4[3], sH[st] + o);
                LDSM4(bl4[0], bl4[1], bl4[2], bl4[3], sL[st] + o);
                #pragma unroll
                for (int mt = 0; mt < 2; mt++) {
                    MMA(sacc[mt][2*p], qh[mt][kk][0], qh[mt][kk][1], qh[mt][kk][2],
                        qh[mt][kk][3], bh4[0], bh4[1]);
                    MMA(sacc[mt][2*p], qh[mt][kk][0], qh[mt][kk][1], qh[mt][kk][2],
                        qh[mt][kk][3], bl4[0], bl4[1]);
                    MMA(sacc[mt][2*p], ql[mt][kk][0], ql[mt][kk][1], ql[mt][kk][2],
                        ql[mt][kk][3], bh4[0], bh4[1]);
                    MMA(sacc[mt][2*p+1], qh[mt][kk][0], qh[mt][kk][1], qh[mt][kk][2],
                        qh[mt][kk][3], bh4[2], bh4[3]);
                    MMA(sacc[mt][2*p+1], qh[mt][kk][0], qh[mt][kk][1], qh[mt][kk][2],
                        qh[mt][kk][3], bl4[2], bl4[3]);
                    MMA(sacc[mt][2*p+1], ql[mt][kk][0], ql[mt][kk][1], ql[mt][kk][2],
                        ql[mt][kk][3], bh4[2], bh4[3]);
                }
            }

        // ---- online softmax per mt ----
        #pragma unroll
        for (int mt = 0; mt < 2; mt++) {
            float mx0 = -1e30f, mx1 = -1e30f;
            #pragma unroll
            for (int nt = 0; nt < 8; nt++) {
                mx0 = fmaxf(mx0, fmaxf(sacc[mt][nt][0], sacc[mt][nt][1]));
                mx1 = fmaxf(mx1, fmaxf(sacc[mt][nt][2], sacc[mt][nt][3]));
            }
            mx0 = fmaxf(mx0, __shfl_xor_sync(0xffffffffu, mx0, 1));
            mx0 = fmaxf(mx0, __shfl_xor_sync(0xffffffffu, mx0, 2));
            mx1 = fmaxf(mx1, __shfl_xor_sync(0xffffffffu, mx1, 1));
            mx1 = fmaxf(mx1, __shfl_xor_sync(0xffffffffu, mx1, 2));
            const float mn0 = fmaxf(mr[mt][0], 0.125f * mx0);
            const float mn1 = fmaxf(mr[mt][1], 0.125f * mx1);
            const float c0 = __expf(mr[mt][0] - mn0);
            const float c1 = __expf(mr[mt][1] - mn1);
            float s0 = 0.f, s1 = 0.f;
            #pragma unroll
            for (int nt = 0; nt < 8; nt++) {
                sacc[mt][nt][0] = __expf(fmaf(0.125f, sacc[mt][nt][0], -mn0));
                sacc[mt][nt][1] = __expf(fmaf(0.125f, sacc[mt][nt][1], -mn0));
                sacc[mt][nt][2] = __expf(fmaf(0.125f, sacc[mt][nt][2], -mn1));
                sacc[mt][nt][3] = __expf(fmaf(0.125f, sacc[mt][nt][3], -mn1));
                s0 += sacc[mt][nt][0] + sacc[mt][nt][1];
                s1 += sacc[mt][nt][2] + sacc[mt][nt][3];
            }
            s0 += __shfl_xor_sync(0xffffffffu, s0, 1);
            s0 += __shfl_xor_sync(0xffffffffu, s0, 2);
            s1 += __shfl_xor_sync(0xffffffffu, s1, 1);
            s1 += __shfl_xor_sync(0xffffffffu, s1, 2);
            lsum[mt][0] = lsum[mt][0] * c0 + s0;
            lsum[mt][1] = lsum[mt][1] * c1 + s1;
            mr[mt][0] = mn0;
            mr[mt][1] = mn1;
            #pragma unroll
            for (int dt = 0; dt < 8; dt++) {
                oacc[mt][dt][0] *= c0; oacc[mt][dt][1] *= c0;
                oacc[mt][dt][2] *= c1; oacc[mt][dt][3] *= c1;
            }
        }

        // ---- O += P V  (P repacked from registers; V = K tile via trans) ----
        #pragma unroll
        for (int kk = 0; kk < 4; kk++) {
            uint32_t pa[2][8];
            #pragma unroll
            for (int mt = 0; mt < 2; mt++) {
                const float p00 = sacc[mt][2*kk][0],   p01 = sacc[mt][2*kk][1];
                const float p02 = sacc[mt][2*kk][2],   p03 = sacc[mt][2*kk][3];
                const float p10 = sacc[mt][2*kk+1][0], p11 = sacc[mt][2*kk+1][1];
                const float p12 = sacc[mt][2*kk+1][2], p13 = sacc[mt][2*kk+1][3];
                pa[mt][0] = pk(p00, p01); pa[mt][1] = pk(p02, p03);
                pa[mt][2] = pk(p10, p11); pa[mt][3] = pk(p12, p13);
                pa[mt][4] = pk(p00 - bfrnd(p00), p01 - bfrnd(p01));
                pa[mt][5] = pk(p02 - bfrnd(p02), p03 - bfrnd(p03));
                pa[mt][6] = pk(p10 - bfrnd(p10), p11 - bfrnd(p11));
                pa[mt][7] = pk(p12 - bfrnd(p12), p13 - bfrnd(p13));
            }
            #pragma unroll
            for (int dp = 0; dp < 4; dp++) {
                const int vr = kk * 16 + (lane & 7) + (((lane >> 3) & 1) << 3);
                const int vc = dp * 16 + ((lane >> 4) << 3);
                const uint32_t o = (uint32_t)(vr * ASTR + vc) * 2;
                uint32_t vh4[4], vl4[4];
                LDSM4T(vh4[0], vh4[1], vh4[2], vh4[3], sH[st] + o);
                LDSM4T(vl4[0], vl4[1], vl4[2], vl4[3], sL[st] + o);
                #pragma unroll
                for (int mt = 0; mt < 2; mt++) {
                    MMA(oacc[mt][2*dp], pa[mt][0], pa[mt][1], pa[mt][2], pa[mt][3],
                        vh4[0], vh4[1]);
                    MMA(oacc[mt][2*dp], pa[mt][0], pa[mt][1], pa[mt][2], pa[mt][3],
                        vl4[0], vl4[1]);
                    MMA(oacc[mt][2*dp], pa[mt][4], pa[mt][5], pa[mt][6], pa[mt][7],
                        vh4[0], vh4[1]);
                    MMA(oacc[mt][2*dp+1], pa[mt][0], pa[mt][1], pa[mt][2], pa[mt][3],
                        vh4[2], vh4[3]);
                    MMA(oacc[mt][2*dp+1], pa[mt][0], pa[mt][1], pa[mt][2], pa[mt][3],
                        vl4[2], vl4[3]);
                    MMA(oacc[mt][2*dp+1], pa[mt][4], pa[mt][5], pa[mt][6], pa[mt][7],
                        vh4[2], vh4[3]);
                }
            }
        }

        __syncthreads();
        if (t + 2 < 32) {
            const size_t off = qbase + (size_t)((t + 2) * 64 + krow) * D_ + kseg * 32;
            const uint32_t dh = sH[st] + (uint32_t)(krow * 144 + kseg * 64);
            const uint32_t dl = sL[st] + (uint32_t)(krow * 144 + kseg * 64);
            #pragma unroll
            for (int i = 0; i < 4; i++) {
                cpa16(dh + i * 16, g_qh + off + i * 8);
                cpa16(dl + i * 16, g_ql + off + i * 8);
            }
            CPCOMMIT();
        }
    }

    // ---- epilogue: normalize, split hi/lo, write ----
    #pragma unroll
    for (int mt = 0; mt < 2; mt++) {
        const float i0 = 1.f / lsum[mt][0];
        const float i1 = 1.f / lsum[mt][1];
        const int r = t0 + wid * 32 + mt * 16 + (lane >> 2);
        #pragma unroll
        for (int dt = 0; dt < 8; dt++) {
            const int c = dt * 8 + 2 * (lane & 3);
            const float v0 = oacc[mt][dt][0] * i0, v1 = oacc[mt][dt][1] * i0;
            const float v2 = oacc[mt][dt][2] * i1, v3 = oacc[mt][dt][3] * i1;
            const size_t ia = qbase + (size_t)r * D_ + c;
            const size_t ib = qbase + (size_t)(r + 8) * D_ + c;
            *reinterpret_cast<uint32_t*>(&g_ah[ia]) = pk(v0, v1);
            *reinterpret_cast<uint32_t*>(&g_al[ia]) = pk(v0 - bfrnd(v0), v1 - bfrnd(v1));
            *reinterpret_cast<uint32_t*>(&g_ah[ib]) = pk(v2, v3);
            *reinterpret_cast<uint32_t*>(&g_al[ib]) = pk(v2 - bfrnd(v2), v3 - bfrnd(v3));
        }
    }
}

// ---------------------------------------------------------------------------
extern "C" void kernel_launch(void* const* d_in, const int* in_sizes, int n_in,
                              void* d_out, int out_size)
{
    const float* x  = (const float*)d_in[0];
    const float* Wq = (const float*)d_in[1];
    const float* Wu = (const float*)d_in[2];
    const float* bu = (const float*)d_in[3];
    float* out = (float*)d_out;

    dim3 gg(D_ / 64, M_ / 128);    // (16, 64)
    dim3 gat(T_ / 128, B_ * H_);   // (16, 64)

    k_gemm_q<<<gg, 256>>>(x, Wq);
    k_attn2<<<gat, 128>>>();
    k_gemm_o<<<gg, 256>>>(Wu, bu, out);
}

// round 7
// speedup vs baseline: 59.0620x; 1.1100x over previous
#include <cuda_runtime.h>
#include <cuda_bf16.h>
#include <cstdint>

#define B_ 4
#define T_ 2048
#define D_ 1024
#define H_ 16
#define S_ 64
#define M_ (B_ * T_)   // 8192

// Pre-split bf16 hi/lo scratch (static device globals; no runtime alloc)
__device__ __nv_bfloat16 g_xh [(size_t)M_ * D_];
__device__ __nv_bfloat16 g_xl [(size_t)M_ * D_];
__device__ __nv_bfloat16 g_wqh[(size_t)D_ * D_];
__device__ __nv_bfloat16 g_wql[(size_t)D_ * D_];
__device__ __nv_bfloat16 g_wuh[(size_t)D_ * D_];
__device__ __nv_bfloat16 g_wul[(size_t)D_ * D_];
__device__ __nv_bfloat16 g_qh [(size_t)M_ * D_];
__device__ __nv_bfloat16 g_ql [(size_t)M_ * D_];
__device__ __nv_bfloat16 g_ah [(size_t)M_ * D_];
__device__ __nv_bfloat16 g_al [(size_t)M_ * D_];

__device__ __forceinline__ uint32_t smem_u32(const void* p) {
    uint32_t a;
    asm("{ .reg .u64 t; cvta.to.shared.u64 t, %1; cvt.u32.u64 %0, t; }"
        : "=r"(a) : "l"(p));
    return a;
}
__device__ __forceinline__ uint32_t pk(float lo_val, float hi_val) {
    uint32_t d;
    asm("cvt.rn.bf16x2.f32 %0, %1, %2;" : "=r"(d) : "f"(hi_val), "f"(lo_val));
    return d;
}
__device__ __forceinline__ float bfrnd(float x) {
    return __bfloat162float(__float2bfloat16(x));
}
__device__ __forceinline__ void cvt44(float4 v, uint2& h, uint2& l) {
    h.x = pk(v.x, v.y);
    h.y = pk(v.z, v.w);
    l.x = pk(v.x - bfrnd(v.x), v.y - bfrnd(v.y));
    l.y = pk(v.z - bfrnd(v.z), v.w - bfrnd(v.w));
}
__device__ __forceinline__ void cpa16(uint32_t d, const __nv_bfloat16* s) {
    asm volatile("cp.async.ca.shared.global [%0], [%1], 16;"
                 :: "r"(d), "l"((size_t)__cvta_generic_to_global(s)));
}
#define CPCOMMIT() asm volatile("cp.async.commit_group;")
#define CPWAIT0()  asm volatile("cp.async.wait_group 0;")
#define CPWAIT1()  asm volatile("cp.async.wait_group 1;")

#define LDSM4(r0, r1, r2, r3, a) \
    asm volatile("ldmatrix.sync.aligned.m8n8.x4.shared.b16 {%0,%1,%2,%3}, [%4];" \
        : "=r"(r0), "=r"(r1), "=r"(r2), "=r"(r3) : "r"(a))
#define LDSM4T(r0, r1, r2, r3, a) \
    asm volatile("ldmatrix.sync.aligned.m8n8.x4.trans.shared.b16 {%0,%1,%2,%3}, [%4];" \
        : "=r"(r0), "=r"(r1), "=r"(r2), "=r"(r3) : "r"(a))
#define MMA(c, a0, a1, a2, a3, b0, b1) \
    asm volatile("mma.sync.aligned.m16n8k16.row.col.f32.bf16.bf16.f32 " \
        "{%0,%1,%2,%3}, {%4,%5,%6,%7}, {%8,%9}, {%0,%1,%2,%3};" \
        : "+f"((c)[0]), "+f"((c)[1]), "+f"((c)[2]), "+f"((c)[3]) \
        : "r"(a0), "r"(a1), "r"(a2), "r"(a3), "r"(b0), "r"(b1))

// ---------------------------------------------------------------------------
// Elementwise fp32 -> bf16 hi/lo split
// ---------------------------------------------------------------------------
__global__ void __launch_bounds__(256) k_split(const float4* __restrict__ src,
                                               uint2* __restrict__ h,
                                               uint2* __restrict__ l, int n4)
{
    const int i = blockIdx.x * 256 + threadIdx.x;
    if (i < n4) {
        uint2 hh, ll;
        cvt44(src[i], hh, ll);
        h[i] = hh;
        l[i] = ll;
    }
}

// ---------------------------------------------------------------------------
// Unified bf16x3 GEMM, cp.async double-buffered.
// C[m][n] = sum_k (Ah+Al)[m][k] * (Bh+Bl)[n][k]  (+bias or split output)
// CTA 128m x 64n, K-chunk 32, 2 stages, 256 threads, warp = m32 x n32.
// smem/stage: AH(128x40) AL BH(64x40) BL bf16 = 30720 B; 2 stages = 61440 B.
// ---------------------------------------------------------------------------
#define GSTR 40
#define STAGE_B 30720u
#define GE_SMEM (2 * STAGE_B)

template<bool SPLIT>
__global__ void __launch_bounds__(256) k_gemm_bb(
    const __nv_bfloat16* __restrict__ Ah, const __nv_bfloat16* __restrict__ Al,
    const __nv_bfloat16* __restrict__ Bh, const __nv_bfloat16* __restrict__ Bl,
    const float* __restrict__ bias, float* __restrict__ C,
    __nv_bfloat16* __restrict__ Oh, __nv_bfloat16* __restrict__ Ol)
{
    extern __shared__ __align__(16) __nv_bfloat16 smg[];
    const uint32_t sb = smem_u32(smg);

    const int tid = threadIdx.x, lane = tid & 31, wid = tid >> 5;
    const int wm = wid & 3, wn = wid >> 2;
    const int m0 = blockIdx.y << 7, n0 = blockIdx.x << 6;

    // per-thread load mapping
    const int arow0 = tid >> 2, ac = tid & 3;           // A: idx=tid, tid+256
    const int arow1 = (tid + 256) >> 2;
    const int brow = tid >> 2;                           // B: idx=tid

    auto issue_chunk = [&](int t, int st) {
        const int k0 = t * 32;
        const uint32_t base = sb + (uint32_t)st * STAGE_B;
        {
            const size_t s0 = (size_t)(m0 + arow0) * 1024 + k0 + ac * 8;
            const uint32_t d0 = base + (uint32_t)(arow0 * 80 + ac * 16);
            cpa16(d0, Ah + s0);
            cpa16(d0 + 10240u, Al + s0);
            const size_t s1 = (size_t)(m0 + arow1) * 1024 + k0 + ac * 8;
            const uint32_t d1 = base + (uint32_t)(arow1 * 80 + ac * 16);
            cpa16(d1, Ah + s1);
            cpa16(d1 + 10240u, Al + s1);
        }
        {
            const size_t s2 = (size_t)(n0 + brow) * 1024 + k0 + ac * 8;
            const uint32_t d2 = base + 20480u + (uint32_t)(brow * 80 + ac * 16);
            cpa16(d2, Bh + s2);
            cpa16(d2 + 5120u, Bl + s2);
        }
    };

    // prime pipeline
    issue_chunk(0, 0); CPCOMMIT();
    issue_chunk(1, 1); CPCOMMIT();

    float acc[2][4][4] = {};

    for (int t = 0; t < 32; t++) {
        const int st = t & 1;
        if (t == 31) { CPWAIT0(); } else { CPWAIT1(); }
        __syncthreads();

        const uint32_t sAH = sb + (uint32_t)st * STAGE_B;
        const uint32_t sAL = sAH + 10240u;
        const uint32_t sBH = sAH + 20480u;
        const uint32_t sBL = sAH + 25600u;

        #pragma unroll
        for (int kk = 0; kk < 32; kk += 16) {
            uint32_t ah[2][4], al[2][4];
            #pragma unroll
            for (int mt = 0; mt < 2; mt++) {
                const int r = wm * 32 + mt * 16 + (lane & 15);
                const int c = kk + ((lane >> 4) << 3);
                const uint32_t off = (uint32_t)(r * GSTR + c) * 2;
                LDSM4(ah[mt][0], ah[mt][1], ah[mt][2], ah[mt][3], sAH + off);
                LDSM4(al[mt][0], al[mt][1], al[mt][2], al[mt][3], sAL + off);
            }
            uint32_t bh[4][2], bl[4][2];
            #pragma unroll
            for (int p = 0; p < 2; p++) {
                const int r = wn * 32 + p * 16 + (lane & 7) + ((lane >> 4) << 3);
                const int c = kk + (((lane >> 3) & 1) << 3);
                const uint32_t off = (uint32_t)(r * GSTR + c) * 2;
                LDSM4(bh[2*p][0], bh[2*p][1], bh[2*p+1][0], bh[2*p+1][1], sBH + off);
                LDSM4(bl[2*p][0], bl[2*p][1], bl[2*p+1][0], bl[2*p+1][1], sBL + off);
            }
            #pragma unroll
            for (int mt = 0; mt < 2; mt++)
                #pragma unroll
                for (int nt = 0; nt < 4; nt++) {
                    MMA(acc[mt][nt], ah[mt][0], ah[mt][1], ah[mt][2], ah[mt][3],
                        bh[nt][0], bh[nt][1]);
                    MMA(acc[mt][nt], ah[mt][0], ah[mt][1], ah[mt][2], ah[mt][3],
                        bl[nt][0], bl[nt][1]);
                    MMA(acc[mt][nt], al[mt][0], al[mt][1], al[mt][2], al[mt][3],
                        bh[nt][0], bh[nt][1]);
                }
        }

        __syncthreads();
        if (t + 2 < 32) {
            issue_chunk(t + 2, st);
            CPCOMMIT();
        }
    }

    // epilogue
    #pragma unroll
    for (int mt = 0; mt < 2; mt++) {
        const int r = m0 + wm * 32 + mt * 16 + (lane >> 2);
        #pragma unroll
        for (int nt = 0; nt < 4; nt++) {
            const int c = n0 + wn * 32 + nt * 8 + 2 * (lane & 3);
            const float a0 = acc[mt][nt][0], a1 = acc[mt][nt][1];
            const float a2 = acc[mt][nt][2], a3 = acc[mt][nt][3];
            const size_t ia = (size_t)r * 1024 + c;
            const size_t ib = (size_t)(r + 8) * 1024 + c;
            if (SPLIT) {
                *reinterpret_cast<uint32_t*>(&Oh[ia]) = pk(a0, a1);
                *reinterpret_cast<uint32_t*>(&Ol[ia]) = pk(a0 - bfrnd(a0), a1 - bfrnd(a1));
                *reinterpret_cast<uint32_t*>(&Oh[ib]) = pk(a2, a3);
                *reinterpret_cast<uint32_t*>(&Ol[ib]) = pk(a2 - bfrnd(a2), a3 - bfrnd(a3));
            } else {
                const float b0 = bias[c], b1 = bias[c + 1];
                *reinterpret_cast<float2*>(&C[ia]) = make_float2(a0 + b0, a1 + b1);
                *reinterpret_cast<float2*>(&C[ib]) = make_float2(a2 + b0, a3 + b1);
            }
        }
    }
}

// ---------------------------------------------------------------------------
// Flash attention: 128 threads, 4 warps, warp = m32. Key tile = 64,
// cp.async double-buffered. Q fragments cached in registers for all tiles.
// ---------------------------------------------------------------------------
#define ASTR 72

__global__ void __launch_bounds__(128) k_attn2()
{
    __shared__ __align__(16) __nv_bfloat16 smk[4 * 64 * ASTR];  // 36864 B
    const uint32_t sb = smem_u32(smk);
    const uint32_t sH[2] = {sb, sb + 18432u};
    const uint32_t sL[2] = {sb + 9216u, sb + 27648u};

    const int tid = threadIdx.x, lane = tid & 31, wid = tid >> 5;
    const int bh = blockIdx.y, b = bh >> 4, h = bh & 15;
    const int t0 = blockIdx.x << 7;
    const size_t qbase = (size_t)b * T_ * D_ + (size_t)h * S_;

    // Q rows [t0, t0+128): rows 0-63 -> stage0, 64-127 -> stage1
    {
        const int stg = tid >> 6, qlr = tid & 63;
        const size_t off = qbase + (size_t)(t0 + tid) * D_;
        const uint32_t dh = sH[stg] + (uint32_t)qlr * 144u;
        const uint32_t dl = sL[stg] + (uint32_t)qlr * 144u;
        #pragma unroll
        for (int i = 0; i < 8; i++) {
            cpa16(dh + i * 16, g_qh + off + i * 8);
            cpa16(dl + i * 16, g_ql + off + i * 8);
        }
        CPCOMMIT();
    }
    CPWAIT0();
    __syncthreads();

    // Q fragments -> registers (reused for all 32 key tiles)
    uint32_t qh[2][4][4], ql[2][4][4];
    {
        const int stg = wid >> 1, rb = (wid & 1) << 5;
        #pragma unroll
        for (int mt = 0; mt < 2; mt++)
            #pragma unroll
            for (int kk = 0; kk < 4; kk++) {
                const int ar = rb + mt * 16 + (lane & 15);
                const int ac = kk * 16 + ((lane >> 4) << 3);
                const uint32_t o = (uint32_t)(ar * ASTR + ac) * 2;
                LDSM4(qh[mt][kk][0], qh[mt][kk][1], qh[mt][kk][2], qh[mt][kk][3],
                      sH[stg] + o);
                LDSM4(ql[mt][kk][0], ql[mt][kk][1], ql[mt][kk][2], ql[mt][kk][3],
                      sL[stg] + o);
            }
    }
    __syncthreads();

    float oacc[2][8][4] = {};
    float mr[2][2] = {{-1e30f, -1e30f}, {-1e30f, -1e30f}};
    float lsum[2][2] = {};

    const int krow = tid >> 1, kseg = tid & 1;
    #pragma unroll
    for (int t = 0; t < 2; t++) {
        const size_t off = qbase + (size_t)(t * 64 + krow) * D_ + kseg * 32;
        const uint32_t dh = sH[t] + (uint32_t)(krow * 144 + kseg * 64);
        const uint32_t dl = sL[t] + (uint32_t)(krow * 144 + kseg * 64);
        #pragma unroll
        for (int i = 0; i < 4; i++) {
            cpa16(dh + i * 16, g_qh + off + i * 8);
            cpa16(dl + i * 16, g_ql + off + i * 8);
        }
        CPCOMMIT();
    }

    for (int t = 0; t < 32; t++) {
        const int st = t & 1;
        if (t == 31) { CPWAIT0(); } else { CPWAIT1(); }
        __syncthreads();

        // ---- S = Q K^T ----
        float sacc[2][8][4] = {};
        #pragma unroll
        for (int kk = 0; kk < 4; kk++)
            #pragma unroll
            for (int p = 0; p < 4; p++) {
                const int br = p * 16 + (lane & 7) + ((lane >> 4) << 3);
                const int bc = kk * 16 + (((lane >> 3) & 1) << 3);
                const uint32_t o = (uint32_t)(br * ASTR + bc) * 2;
                uint32_t bh4[4], bl4[4];
                LDSM4(bh4[0], bh4[1], bh4[2], bh4[3], sH[st] + o);
                LDSM4(bl4[0], bl4[1], bl4[2], bl4[3], sL[st] + o);
                #pragma unroll
                for (int mt = 0; mt < 2; mt++) {
                    MMA(sacc[mt][2*p], qh[mt][kk][0], qh[mt][kk][1], qh[mt][kk][2],
                        qh[mt][kk][3], bh4[0], bh4[1]);
                    MMA(sacc[mt][2*p], qh[mt][kk][0], qh[mt][kk][1], qh[mt][kk][2],
                        qh[mt][kk][3], bl4[0], bl4[1]);
                    MMA(sacc[mt][2*p], ql[mt][kk][0], ql[mt][kk][1], ql[mt][kk][2],
                        ql[mt][kk][3], bh4[0], bh4[1]);
                    MMA(sacc[mt][2*p+1], qh[mt][kk][0], qh[mt][kk][1], qh[mt][kk][2],
                        qh[mt][kk][3], bh4[2], bh4[3]);
                    MMA(sacc[mt][2*p+1], qh[mt][kk][0], qh[mt][kk][1], qh[mt][kk][2],
                        qh[mt][kk][3], bl4[2], bl4[3]);
                    MMA(sacc[mt][2*p+1], ql[mt][kk][0], ql[mt][kk][1], ql[mt][kk][2],
                        ql[mt][kk][3], bh4[2], bh4[3]);
                }
            }

        // ---- online softmax per mt ----
        #pragma unroll
        for (int mt = 0; mt < 2; mt++) {
            float mx0 = -1e30f, mx1 = -1e30f;
            #pragma unroll
            for (int nt = 0; nt < 8; nt++) {
                mx0 = fmaxf(mx0, fmaxf(sacc[mt][nt][0], sacc[mt][nt][1]));
                mx1 = fmaxf(mx1, fmaxf(sacc[mt][nt][2], sacc[mt][nt][3]));
            }
            mx0 = fmaxf(mx0, __shfl_xor_sync(0xffffffffu, mx0, 1));
            mx0 = fmaxf(mx0, __shfl_xor_sync(0xffffffffu, mx0, 2));
            mx1 = fmaxf(mx1, __shfl_xor_sync(0xffffffffu, mx1, 1));
            mx1 = fmaxf(mx1, __shfl_xor_sync(0xffffffffu, mx1, 2));
            const float mn0 = fmaxf(mr[mt][0], 0.125f * mx0);
            const float mn1 = fmaxf(mr[mt][1], 0.125f * mx1);
            const float c0 = __expf(mr[mt][0] - mn0);
            const float c1 = __expf(mr[mt][1] - mn1);
            float s0 = 0.f, s1 = 0.f;
            #pragma unroll
            for (int nt = 0; nt < 8; nt++) {
                sacc[mt][nt][0] = __expf(fmaf(0.125f, sacc[mt][nt][0], -mn0));
                sacc[mt][nt][1] = __expf(fmaf(0.125f, sacc[mt][nt][1], -mn0));
                sacc[mt][nt][2] = __expf(fmaf(0.125f, sacc[mt][nt][2], -mn1));
                sacc[mt][nt][3] = __expf(fmaf(0.125f, sacc[mt][nt][3], -mn1));
                s0 += sacc[mt][nt][0] + sacc[mt][nt][1];
                s1 += sacc[mt][nt][2] + sacc[mt][nt][3];
            }
            s0 += __shfl_xor_sync(0xffffffffu, s0, 1);
            s0 += __shfl_xor_sync(0xffffffffu, s0, 2);
            s1 += __shfl_xor_sync(0xffffffffu, s1, 1);
            s1 += __shfl_xor_sync(0xffffffffu, s1, 2);
            lsum[mt][0] = lsum[mt][0] * c0 + s0;
            lsum[mt][1] = lsum[mt][1] * c1 + s1;
            mr[mt][0] = mn0;
            mr[mt][1] = mn1;
            #pragma unroll
            for (int dt = 0; dt < 8; dt++) {
                oacc[mt][dt][0] *= c0; oacc[mt][dt][1] *= c0;
                oacc[mt][dt][2] *= c1; oacc[mt][dt][3] *= c1;
            }
        }

        // ---- O += P V ----
        #pragma unroll
        for (int kk = 0; kk < 4; kk++) {
            uint32_t pa[2][8];
            #pragma unroll
            for (int mt = 0; mt < 2; mt++) {
                const float p00 = sacc[mt][2*kk][0],   p01 = sacc[mt][2*kk][1];
                const float p02 = sacc[mt][2*kk][2],   p03 = sacc[mt][2*kk][3];
                const float p10 = sacc[mt][2*kk+1][0], p11 = sacc[mt][2*kk+1][1];
                const float p12 = sacc[mt][2*kk+1][2], p13 = sacc[mt][2*kk+1][3];
                pa[mt][0] = pk(p00, p01); pa[mt][1] = pk(p02, p03);
                pa[mt][2] = pk(p10, p11); pa[mt][3] = pk(p12, p13);
                pa[mt][4] = pk(p00 - bfrnd(p00), p01 - bfrnd(p01));
                pa[mt][5] = pk(p02 - bfrnd(p02), p03 - bfrnd(p03));
                pa[mt][6] = pk(p10 - bfrnd(p10), p11 - bfrnd(p11));
                pa[mt][7] = pk(p12 - bfrnd(p12), p13 - bfrnd(p13));
            }
            #pragma unroll
            for (int dp = 0; dp < 4; dp++) {
                const int vr = kk * 16 + (lane & 7) + (((lane >> 3) & 1) << 3);
                const int vc = dp * 16 + ((lane >> 4) << 3);
                const uint32_t o = (uint32_t)(vr * ASTR + vc) * 2;
                uint32_t vh4[4], vl4[4];
                LDSM4T(vh4[0], vh4[1], vh4[2], vh4[3], sH[st] + o);
                LDSM4T(vl4[0], vl4[1], vl4[2], vl4[3], sL[st] + o);
                #pragma unroll
                for (int mt = 0; mt < 2; mt++) {
                    MMA(oacc[mt][2*dp], pa[mt][0], pa[mt][1], pa[mt][2], pa[mt][3],
                        vh4[0], vh4[1]);
                    MMA(oacc[mt][2*dp], pa[mt][0], pa[mt][1], pa[mt][2], pa[mt][3],
                        vl4[0], vl4[1]);
                    MMA(oacc[mt][2*dp], pa[mt][4], pa[mt][5], pa[mt][6], pa[mt][7],
                        vh4[0], vh4[1]);
                    MMA(oacc[mt][2*dp+1], pa[mt][0], pa[mt][1], pa[mt][2], pa[mt][3],
                        vh4[2], vh4[3]);
                    MMA(oacc[mt][2*dp+1], pa[mt][0], pa[mt][1], pa[mt][2], pa[mt][3],
                        vl4[2], vl4[3]);
                    MMA(oacc[mt][2*dp+1], pa[mt][4], pa[mt][5], pa[mt][6], pa[mt][7],
                        vh4[2], vh4[3]);
                }
            }
        }

        __syncthreads();
        if (t + 2 < 32) {
            const size_t off = qbase + (size_t)((t + 2) * 64 + krow) * D_ + kseg * 32;
            const uint32_t dh = sH[st] + (uint32_t)(krow * 144 + kseg * 64);
            const uint32_t dl = sL[st] + (uint32_t)(krow * 144 + kseg * 64);
            #pragma unroll
            for (int i = 0; i < 4; i++) {
                cpa16(dh + i * 16, g_qh + off + i * 8);
                cpa16(dl + i * 16, g_ql + off + i * 8);
            }
            CPCOMMIT();
        }
    }

    // ---- epilogue: normalize, split hi/lo, write ----
    #pragma unroll
    for (int mt = 0; mt < 2; mt++) {
        const float i0 = 1.f / lsum[mt][0];
        const float i1 = 1.f / lsum[mt][1];
        const int r = t0 + wid * 32 + mt * 16 + (lane >> 2);
        #pragma unroll
        for (int dt = 0; dt < 8; dt++) {
            const int c = dt * 8 + 2 * (lane & 3);
            const float v0 = oacc[mt][dt][0] * i0, v1 = oacc[mt][dt][1] * i0;
            const float v2 = oacc[mt][dt][2] * i1, v3 = oacc[mt][dt][3] * i1;
            const size_t ia = qbase + (size_t)r * D_ + c;
            const size_t ib = qbase + (size_t)(r + 8) * D_ + c;
            *reinterpret_cast<uint32_t*>(&g_ah[ia]) = pk(v0, v1);
            *reinterpret_cast<uint32_t*>(&g_al[ia]) = pk(v0 - bfrnd(v0), v1 - bfrnd(v1));
            *reinterpret_cast<uint32_t*>(&g_ah[ib]) = pk(v2, v3);
            *reinterpret_cast<uint32_t*>(&g_al[ib]) = pk(v2 - bfrnd(v2), v3 - bfrnd(v3));
        }
    }
}

// ---------------------------------------------------------------------------
extern "C" void kernel_launch(void* const* d_in, const int* in_sizes, int n_in,
                              void* d_out, int out_size)
{
    const float* x  = (const float*)d_in[0];
    const float* Wq = (const float*)d_in[1];
    const float* Wu = (const float*)d_in[2];
    const float* bu = (const float*)d_in[3];
    float* out = (float*)d_out;

    cudaFuncSetAttribute(k_gemm_bb<true>,
                         cudaFuncAttributeMaxDynamicSharedMemorySize, GE_SMEM);
    cudaFuncSetAttribute(k_gemm_bb<false>,
                         cudaFuncAttributeMaxDynamicSharedMemorySize, GE_SMEM);

    __nv_bfloat16 *xh, *xl, *wqh, *wql, *wuh, *wul, *qh, *ql, *ah, *al;
    cudaGetSymbolAddress((void**)&xh,  g_xh);
    cudaGetSymbolAddress((void**)&xl,  g_xl);
    cudaGetSymbolAddress((void**)&wqh, g_wqh);
    cudaGetSymbolAddress((void**)&wql, g_wql);
    cudaGetSymbolAddress((void**)&wuh, g_wuh);
    cudaGetSymbolAddress((void**)&wul, g_wul);
    cudaGetSymbolAddress((void**)&qh,  g_qh);
    cudaGetSymbolAddress((void**)&ql,  g_ql);
    cudaGetSymbolAddress((void**)&ah,  g_ah);
    cudaGetSymbolAddress((void**)&al,  g_al);

    const int nx4 = M_ * D_ / 4, nw4 = D_ * D_ / 4;
    k_split<<<nx4 / 256, 256>>>((const float4*)x, (uint2*)xh, (uint2*)xl, nx4);
    k_split<<<nw4 / 256, 256>>>((const float4*)Wq, (uint2*)wqh, (uint2*)wql, nw4);
    k_split<<<nw4 / 256, 256>>>((const float4*)Wu, (uint2*)wuh, (uint2*)wul, nw4);

    dim3 gg(D_ / 64, M_ / 128);    // (16, 64)
    dim3 gat(T_ / 128, B_ * H_);   // (16, 64)

    k_gemm_bb<true><<<gg, 256, GE_SMEM>>>(xh, xl, wqh, wql, nullptr, nullptr,
                                          qh, ql);
    k_attn2<<<gat, 128>>>();
    k_gemm_bb<false><<<gg, 256, GE_SMEM>>>(ah, al, wuh, wul, bu, out,
                                           nullptr, nullptr);
}

// round 8
// speedup vs baseline: 133.6135x; 2.2623x over previous
#include <cuda_runtime.h>
#include <cuda_fp16.h>
#include <cstdint>

#define B_ 4
#define T_ 2048
#define D_ 1024
#define H_ 16
#define S_ 64
#define M_ (B_ * T_)   // 8192

// fp16 scratch (static device globals; no runtime alloc)
__device__ __half g_xf [(size_t)M_ * D_];
__device__ __half g_wqf[(size_t)D_ * D_];
__device__ __half g_wuf[(size_t)D_ * D_];
__device__ __half g_qf [(size_t)M_ * D_];
__device__ __half g_af [(size_t)M_ * D_];

__device__ __forceinline__ uint32_t smem_u32(const void* p) {
    uint32_t a;
    asm("{ .reg .u64 t; cvta.to.shared.u64 t, %1; cvt.u32.u64 %0, t; }"
        : "=r"(a) : "l"(p));
    return a;
}
// pack two fp32 -> half2 (element0 = lo_val)
__device__ __forceinline__ uint32_t pkh(float lo_val, float hi_val) {
    uint32_t d;
    asm("cvt.rn.f16x2.f32 %0, %1, %2;" : "=r"(d) : "f"(hi_val), "f"(lo_val));
    return d;
}
__device__ __forceinline__ void cpa16(uint32_t d, const __half* s) {
    asm volatile("cp.async.ca.shared.global [%0], [%1], 16;"
                 :: "r"(d), "l"((size_t)__cvta_generic_to_global(s)));
}
#define CPCOMMIT() asm volatile("cp.async.commit_group;")
#define CPWAIT0()  asm volatile("cp.async.wait_group 0;")
#define CPWAIT1()  asm volatile("cp.async.wait_group 1;")

#define LDSM4(r0, r1, r2, r3, a) \
    asm volatile("ldmatrix.sync.aligned.m8n8.x4.shared.b16 {%0,%1,%2,%3}, [%4];" \
        : "=r"(r0), "=r"(r1), "=r"(r2), "=r"(r3) : "r"(a))
#define LDSM4T(r0, r1, r2, r3, a) \
    asm volatile("ldmatrix.sync.aligned.m8n8.x4.trans.shared.b16 {%0,%1,%2,%3}, [%4];" \
        : "=r"(r0), "=r"(r1), "=r"(r2), "=r"(r3) : "r"(a))
#define MMA(c, a0, a1, a2, a3, b0, b1) \
    asm volatile("mma.sync.aligned.m16n8k16.row.col.f32.f16.f16.f32 " \
        "{%0,%1,%2,%3}, {%4,%5,%6,%7}, {%8,%9}, {%0,%1,%2,%3};" \
        : "+f"((c)[0]), "+f"((c)[1]), "+f"((c)[2]), "+f"((c)[3]) \
        : "r"(a0), "r"(a1), "r"(a2), "r"(a3), "r"(b0), "r"(b1))

// ---------------------------------------------------------------------------
// fp32 -> fp16 convert
// ---------------------------------------------------------------------------
__global__ void __launch_bounds__(256) k_cvt(const float4* __restrict__ s,
                                             uint2* __restrict__ d, int n4)
{
    const int i = blockIdx.x * 256 + threadIdx.x;
    if (i < n4) {
        const float4 v = s[i];
        d[i] = make_uint2(pkh(v.x, v.y), pkh(v.z, v.w));
    }
}

// ---------------------------------------------------------------------------
// fp16 GEMM: C[m][n] = sum_k A[m][k]*B[n][k] (+bias / fp16 out).
// CTA 128m x 128n, K-chunk 32, 2-stage cp.async, 256 threads.
// 8 warps: wm(0-3) m32, wn(0-1) n64.
// smem/stage: A 128x40 fp16 (10240 B) + B 128x40 (10240 B) = 20480 B.
// ---------------------------------------------------------------------------
#define GSTR 40
#define GST_B 20480u

template<bool OUTF16>
__global__ void __launch_bounds__(256) k_gemm_h(
    const __half* __restrict__ A, const __half* __restrict__ Bm,
    const float* __restrict__ bias, float* __restrict__ C,
    __half* __restrict__ Of)
{
    __shared__ __align__(16) __half smg[2 * GST_B / 2];
    const uint32_t sb = smem_u32(smg);

    const int tid = threadIdx.x, lane = tid & 31, wid = tid >> 5;
    const int wm = wid & 3, wn = wid >> 2;
    const int m0 = blockIdx.y << 7, n0 = blockIdx.x << 7;

    const int row0 = tid >> 2, row1 = (tid >> 2) + 64, ac = tid & 3;

    auto issue_chunk = [&](int t, int st) {
        const int k0 = t * 32;
        const uint32_t base = sb + (uint32_t)st * GST_B;
        cpa16(base + (uint32_t)(row0 * 80 + ac * 16),
              A + (size_t)(m0 + row0) * 1024 + k0 + ac * 8);
        cpa16(base + (uint32_t)(row1 * 80 + ac * 16),
              A + (size_t)(m0 + row1) * 1024 + k0 + ac * 8);
        cpa16(base + 10240u + (uint32_t)(row0 * 80 + ac * 16),
              Bm + (size_t)(n0 + row0) * 1024 + k0 + ac * 8);
        cpa16(base + 10240u + (uint32_t)(row1 * 80 + ac * 16),
              Bm + (size_t)(n0 + row1) * 1024 + k0 + ac * 8);
    };

    issue_chunk(0, 0); CPCOMMIT();
    issue_chunk(1, 1); CPCOMMIT();

    float acc[2][8][4] = {};

    for (int t = 0; t < 32; t++) {
        const int st = t & 1;
        if (t == 31) { CPWAIT0(); } else { CPWAIT1(); }
        __syncthreads();

        const uint32_t sA = sb + (uint32_t)st * GST_B;
        const uint32_t sB = sA + 10240u;

        #pragma unroll
        for (int kk = 0; kk < 32; kk += 16) {
            uint32_t ah[2][4];
            #pragma unroll
            for (int mt = 0; mt < 2; mt++) {
                const int r = wm * 32 + mt * 16 + (lane & 15);
                const int c = kk + ((lane >> 4) << 3);
                LDSM4(ah[mt][0], ah[mt][1], ah[mt][2], ah[mt][3],
                      sA + (uint32_t)(r * GSTR + c) * 2);
            }
            uint32_t bh[8][2];
            #pragma unroll
            for (int p = 0; p < 4; p++) {
                const int r = wn * 64 + p * 16 + (lane & 7) + ((lane >> 4) << 3);
                const int c = kk + (((lane >> 3) & 1) << 3);
                LDSM4(bh[2*p][0], bh[2*p][1], bh[2*p+1][0], bh[2*p+1][1],
                      sB + (uint32_t)(r * GSTR + c) * 2);
            }
            #pragma unroll
            for (int mt = 0; mt < 2; mt++)
                #pragma unroll
                for (int nt = 0; nt < 8; nt++)
                    MMA(acc[mt][nt], ah[mt][0], ah[mt][1], ah[mt][2], ah[mt][3],
                        bh[nt][0], bh[nt][1]);
        }

        __syncthreads();
        if (t + 2 < 32) { issue_chunk(t + 2, st); CPCOMMIT(); }
    }

    // epilogue
    #pragma unroll
    for (int mt = 0; mt < 2; mt++) {
        const int r = m0 + wm * 32 + mt * 16 + (lane >> 2);
        #pragma unroll
        for (int nt = 0; nt < 8; nt++) {
            const int c = n0 + wn * 64 + nt * 8 + 2 * (lane & 3);
            const float a0 = acc[mt][nt][0], a1 = acc[mt][nt][1];
            const float a2 = acc[mt][nt][2], a3 = acc[mt][nt][3];
            const size_t ia = (size_t)r * 1024 + c;
            const size_t ib = (size_t)(r + 8) * 1024 + c;
            if (OUTF16) {
                *reinterpret_cast<uint32_t*>(&Of[ia]) = pkh(a0, a1);
                *reinterpret_cast<uint32_t*>(&Of[ib]) = pkh(a2, a3);
            } else {
                const float b0 = bias[c], b1 = bias[c + 1];
                *reinterpret_cast<float2*>(&C[ia]) = make_float2(a0 + b0, a1 + b1);
                *reinterpret_cast<float2*>(&C[ib]) = make_float2(a2 + b0, a3 + b1);
            }
        }
    }
}

// ---------------------------------------------------------------------------
// Flash attention, single-pass fp16. 128 threads, 4 warps, warp = m32.
// Key tile 64, cp.async double-buffered; Q fragments live in registers.
// smem: 2 stages of 64 x 72 fp16 (9216 B each).
// ---------------------------------------------------------------------------
#define ASTR 72

__global__ void __launch_bounds__(128) k_attn_h()
{
    __shared__ __align__(16) __half smk[2 * 64 * ASTR];   // 18432 B
    const uint32_t sb = smem_u32(smk);
    const uint32_t sH[2] = {sb, sb + 9216u};

    const int tid = threadIdx.x, lane = tid & 31, wid = tid >> 5;
    const int bh = blockIdx.y, b = bh >> 4, h = bh & 15;
    const int t0 = blockIdx.x << 7;
    const size_t qbase = (size_t)b * T_ * D_ + (size_t)h * S_;

    // Q rows [t0, t0+128): rows 0-63 -> stage0, 64-127 -> stage1
    {
        const int stg = tid >> 6, qlr = tid & 63;
        const size_t off = qbase + (size_t)(t0 + tid) * D_;
        const uint32_t dh = sH[stg] + (uint32_t)qlr * 144u;
        #pragma unroll
        for (int i = 0; i < 8; i++) cpa16(dh + i * 16, g_qf + off + i * 8);
        CPCOMMIT();
    }
    CPWAIT0();
    __syncthreads();

    // Q fragments -> registers
    uint32_t qh[2][4][4];
    {
        const int stg = wid >> 1, rb = (wid & 1) << 5;
        #pragma unroll
        for (int mt = 0; mt < 2; mt++)
            #pragma unroll
            for (int kk = 0; kk < 4; kk++) {
                const int ar = rb + mt * 16 + (lane & 15);
                const int ac = kk * 16 + ((lane >> 4) << 3);
                LDSM4(qh[mt][kk][0], qh[mt][kk][1], qh[mt][kk][2], qh[mt][kk][3],
                      sH[stg] + (uint32_t)(ar * ASTR + ac) * 2);
            }
    }
    __syncthreads();

    float oacc[2][8][4] = {};
    float mr[2][2] = {{-1e30f, -1e30f}, {-1e30f, -1e30f}};
    float lsum[2][2] = {};

    const int krow = tid >> 1, kseg = tid & 1;
    #pragma unroll
    for (int t = 0; t < 2; t++) {
        const size_t off = qbase + (size_t)(t * 64 + krow) * D_ + kseg * 32;
        const uint32_t dh = sH[t] + (uint32_t)(krow * 144 + kseg * 64);
        #pragma unroll
        for (int i = 0; i < 4; i++) cpa16(dh + i * 16, g_qf + off + i * 8);
        CPCOMMIT();
    }

    for (int t = 0; t < 32; t++) {
        const int st = t & 1;
        if (t == 31) { CPWAIT0(); } else { CPWAIT1(); }
        __syncthreads();

        // ---- S = Q K^T ----
        float sacc[2][8][4] = {};
        #pragma unroll
        for (int kk = 0; kk < 4; kk++)
            #pragma unroll
            for (int p = 0; p < 4; p++) {
                const int br = p * 16 + (lane & 7) + ((lane >> 4) << 3);
                const int bc = kk * 16 + (((lane >> 3) & 1) << 3);
                uint32_t bh4[4];
                LDSM4(bh4[0], bh4[1], bh4[2], bh4[3],
                      sH[st] + (uint32_t)(br * ASTR + bc) * 2);
                #pragma unroll
                for (int mt = 0; mt < 2; mt++) {
                    MMA(sacc[mt][2*p], qh[mt][kk][0], qh[mt][kk][1],
                        qh[mt][kk][2], qh[mt][kk][3], bh4[0], bh4[1]);
                    MMA(sacc[mt][2*p+1], qh[mt][kk][0], qh[mt][kk][1],
                        qh[mt][kk][2], qh[mt][kk][3], bh4[2], bh4[3]);
                }
            }

        // ---- online softmax per mt ----
        #pragma unroll
        for (int mt = 0; mt < 2; mt++) {
            float mx0 = -1e30f, mx1 = -1e30f;
            #pragma unroll
            for (int nt = 0; nt < 8; nt++) {
                mx0 = fmaxf(mx0, fmaxf(sacc[mt][nt][0], sacc[mt][nt][1]));
                mx1 = fmaxf(mx1, fmaxf(sacc[mt][nt][2], sacc[mt][nt][3]));
            }
            mx0 = fmaxf(mx0, __shfl_xor_sync(0xffffffffu, mx0, 1));
            mx0 = fmaxf(mx0, __shfl_xor_sync(0xffffffffu, mx0, 2));
            mx1 = fmaxf(mx1, __shfl_xor_sync(0xffffffffu, mx1, 1));
            mx1 = fmaxf(mx1, __shfl_xor_sync(0xffffffffu, mx1, 2));
            const float mn0 = fmaxf(mr[mt][0], 0.125f * mx0);
            const float mn1 = fmaxf(mr[mt][1], 0.125f * mx1);
            const float c0 = __expf(mr[mt][0] - mn0);
            const float c1 = __expf(mr[mt][1] - mn1);
            float s0 = 0.f, s1 = 0.f;
            #pragma unroll
            for (int nt = 0; nt < 8; nt++) {
                sacc[mt][nt][0] = __expf(fmaf(0.125f, sacc[mt][nt][0], -mn0));
                sacc[mt][nt][1] = __expf(fmaf(0.125f, sacc[mt][nt][1], -mn0));
                sacc[mt][nt][2] = __expf(fmaf(0.125f, sacc[mt][nt][2], -mn1));
                sacc[mt][nt][3] = __expf(fmaf(0.125f, sacc[mt][nt][3], -mn1));
                s0 += sacc[mt][nt][0] + sacc[mt][nt][1];
                s1 += sacc[mt][nt][2] + sacc[mt][nt][3];
            }
            s0 += __shfl_xor_sync(0xffffffffu, s0, 1);
            s0 += __shfl_xor_sync(0xffffffffu, s0, 2);
            s1 += __shfl_xor_sync(0xffffffffu, s1, 1);
            s1 += __shfl_xor_sync(0xffffffffu, s1, 2);
            lsum[mt][0] = lsum[mt][0] * c0 + s0;
            lsum[mt][1] = lsum[mt][1] * c1 + s1;
            mr[mt][0] = mn0;
            mr[mt][1] = mn1;
            #pragma unroll
            for (int dt = 0; dt < 8; dt++) {
                oacc[mt][dt][0] *= c0; oacc[mt][dt][1] *= c0;
                oacc[mt][dt][2] *= c1; oacc[mt][dt][3] *= c1;
            }
        }

        // ---- O += P V ----
        #pragma unroll
        for (int kk = 0; kk < 4; kk++) {
            uint32_t pa[2][4];
            #pragma unroll
            for (int mt = 0; mt < 2; mt++) {
                pa[mt][0] = pkh(sacc[mt][2*kk][0],   sacc[mt][2*kk][1]);
                pa[mt][1] = pkh(sacc[mt][2*kk][2],   sacc[mt][2*kk][3]);
                pa[mt][2] = pkh(sacc[mt][2*kk+1][0], sacc[mt][2*kk+1][1]);
                pa[mt][3] = pkh(sacc[mt][2*kk+1][2], sacc[mt][2*kk+1][3]);
            }
            #pragma unroll
            for (int dp = 0; dp < 4; dp++) {
                const int vr = kk * 16 + (lane & 7) + (((lane >> 3) & 1) << 3);
                const int vc = dp * 16 + ((lane >> 4) << 3);
                uint32_t vh4[4];
                LDSM4T(vh4[0], vh4[1], vh4[2], vh4[3],
                       sH[st] + (uint32_t)(vr * ASTR + vc) * 2);
                #pragma unroll
                for (int mt = 0; mt < 2; mt++) {
                    MMA(oacc[mt][2*dp], pa[mt][0], pa[mt][1], pa[mt][2],
                        pa[mt][3], vh4[0], vh4[1]);
                    MMA(oacc[mt][2*dp+1], pa[mt][0], pa[mt][1], pa[mt][2],
                        pa[mt][3], vh4[2], vh4[3]);
                }
            }
        }

        __syncthreads();
        if (t + 2 < 32) {
            const size_t off = qbase + (size_t)((t + 2) * 64 + krow) * D_ + kseg * 32;
            const uint32_t dh = sH[st] + (uint32_t)(krow * 144 + kseg * 64);
            #pragma unroll
            for (int i = 0; i < 4; i++) cpa16(dh + i * 16, g_qf + off + i * 8);
            CPCOMMIT();
        }
    }

    // ---- epilogue: normalize, write fp16 ----
    #pragma unroll
    for (int mt = 0; mt < 2; mt++) {
        const float i0 = 1.f / lsum[mt][0];
        const float i1 = 1.f / lsum[mt][1];
        const int r = t0 + wid * 32 + mt * 16 + (lane >> 2);
        #pragma unroll
        for (int dt = 0; dt < 8; dt++) {
            const int c = dt * 8 + 2 * (lane & 3);
            const size_t ia = qbase + (size_t)r * D_ + c;
            const size_t ib = qbase + (size_t)(r + 8) * D_ + c;
            *reinterpret_cast<uint32_t*>(&g_af[ia]) =
                pkh(oacc[mt][dt][0] * i0, oacc[mt][dt][1] * i0);
            *reinterpret_cast<uint32_t*>(&g_af[ib]) =
                pkh(oacc[mt][dt][2] * i1, oacc[mt][dt][3] * i1);
        }
    }
}

// ---------------------------------------------------------------------------
extern "C" void kernel_launch(void* const* d_in, const int* in_sizes, int n_in,
                              void* d_out, int out_size)
{
    const float* x  = (const float*)d_in[0];
    const float* Wq = (const float*)d_in[1];
    const float* Wu = (const float*)d_in[2];
    const float* bu = (const float*)d_in[3];
    float* out = (float*)d_out;

    __half *xf, *wqf, *wuf, *qf, *af;
    cudaGetSymbolAddress((void**)&xf,  g_xf);
    cudaGetSymbolAddress((void**)&wqf, g_wqf);
    cudaGetSymbolAddress((void**)&wuf, g_wuf);
    cudaGetSymbolAddress((void**)&qf,  g_qf);
    cudaGetSymbolAddress((void**)&af,  g_af);

    const int nx4 = M_ * D_ / 4, nw4 = D_ * D_ / 4;
    k_cvt<<<nx4 / 256, 256>>>((const float4*)x,  (uint2*)xf,  nx4);
    k_cvt<<<nw4 / 256, 256>>>((const float4*)Wq, (uint2*)wqf, nw4);
    k_cvt<<<nw4 / 256, 256>>>((const float4*)Wu, (uint2*)wuf, nw4);

    dim3 gg(D_ / 128, M_ / 128);   // (8, 64)
    dim3 gat(T_ / 128, B_ * H_);   // (16, 64)

    k_gemm_h<true><<<gg, 256>>>(xf, wqf, nullptr, nullptr, qf);
    k_attn_h<<<gat, 128>>>();
    k_gemm_h<false><<<gg, 256>>>(af, wuf, bu, out, nullptr);
}